// round 2
// baseline (speedup 1.0000x reference)
#include <cuda_runtime.h>
#include <cuda_fp16.h>
#include <mma.h>

using namespace nvcuda;

#define ATTN_SCALE 0.044194173824159216f  // 1/sqrt(512)

// ---------------- static device scratch (no allocations allowed) ----------------
__device__ __align__(16) float  g_qkv [768 * 1536];
__device__ __align__(16) float  g_ao  [768 * 512];
__device__ __align__(16) float  g_xs  [768 * 512];
__device__ __align__(16) float  g_q2  [768 * 512];
__device__ __align__(16) __half g_qkh [768 * 512];
__device__ __align__(16) __half g_texth[(size_t)1000 * 96 * 512];
__device__ __align__(16) __half g_Wovh[512 * 512];
__device__ __align__(16) float  g_bov [512];
__device__ __align__(16) __half g_rch [(size_t)64 * 1000 * 512];
__device__ __align__(16) float  g_txt [(size_t)64 * 1000 * 512];
__device__ __align__(16) float  g_part[8 * 64 * 512];
__device__ __align__(16) float  g_h   [64 * 512];

// =======================================================================
// Generic SIMT fp32 GEMM:  C[m,n] = scale * sum_k A[m,k]*B(k,n) + bias[n]
// A row-major [M][lda]; B element (k,n) at B[k*bsk + n*bsn].
// M,N multiples of 64; K multiple of 16. Optional fp32/fp16 outputs.
// =======================================================================
__global__ void gemm_simt(const float* __restrict__ A, int lda,
                          const float* __restrict__ B, int bsk, int bsn,
                          const float* __restrict__ bias, float scale,
                          float* __restrict__ Cf, __half* __restrict__ Ch,
                          int N, int K)
{
    __shared__ float As[64][17];
    __shared__ float Bs[16][68];
    const int tid = threadIdx.x;
    const int m0 = blockIdx.y * 64, n0 = blockIdx.x * 64;
    const int tx = tid & 15, ty = tid >> 4;
    float acc[4][4] = {};
    for (int kk = 0; kk < K; kk += 16) {
        for (int i = tid; i < 1024; i += 256) {
            int r = i >> 4, c = i & 15;
            As[r][c] = A[(size_t)(m0 + r) * lda + kk + c];
        }
        if (bsn == 1) {
            for (int i = tid; i < 1024; i += 256) {
                int r = i >> 6, c = i & 63;
                Bs[r][c] = B[(size_t)(kk + r) * bsk + (n0 + c)];
            }
        } else {
            for (int i = tid; i < 1024; i += 256) {
                int c = i >> 4, r = i & 15;
                Bs[r][c] = B[(size_t)(kk + r) + (size_t)(n0 + c) * bsn];
            }
        }
        __syncthreads();
        #pragma unroll
        for (int k = 0; k < 16; k++) {
            float av[4], bv[4];
            #pragma unroll
            for (int i = 0; i < 4; i++) av[i] = As[ty * 4 + i][k];
            #pragma unroll
            for (int j = 0; j < 4; j++) bv[j] = Bs[k][tx * 4 + j];
            #pragma unroll
            for (int i = 0; i < 4; i++)
                #pragma unroll
                for (int j = 0; j < 4; j++) acc[i][j] += av[i] * bv[j];
        }
        __syncthreads();
    }
    #pragma unroll
    for (int i = 0; i < 4; i++) {
        size_t m = m0 + ty * 4 + i;
        #pragma unroll
        for (int j = 0; j < 4; j++) {
            int n = n0 + tx * 4 + j;
            float v = acc[i][j] * scale + (bias ? bias[n] : 0.f);
            if (Cf) Cf[m * N + n] = v;
            if (Ch) Ch[m * N + n] = __float2half(v);
        }
    }
}

// =======================================================================
// Self-attention over the 12-layer axis, one block per batch element.
// Reads g_qkv rows (l*64+b), writes g_ao rows (b*12+l).
// =======================================================================
__global__ void self_attn_kernel()
{
    extern __shared__ float sh[];
    float* q = sh;
    float* k = q + 12 * 512;
    float* v = k + 12 * 512;
    float* S = v + 12 * 512;   // 144 floats
    const int b = blockIdx.x, tid = threadIdx.x;
    for (int i = tid; i < 12 * 512; i += 128) {
        int l = i >> 9, d = i & 511;
        const float* row = g_qkv + (size_t)(l * 64 + b) * 1536;
        q[i] = row[d]; k[i] = row[512 + d]; v[i] = row[1024 + d];
    }
    __syncthreads();
    for (int i = tid; i < 144; i += 128) {
        int l = i / 12, m = i - l * 12;
        const float* qp = q + l * 512;
        const float* kp = k + m * 512;
        float s = 0.f;
        for (int e = 0; e < 512; e++) s += qp[e] * kp[e];
        S[i] = s * ATTN_SCALE;
    }
    __syncthreads();
    if (tid < 12) {
        float mx = -1e30f;
        for (int m = 0; m < 12; m++) mx = fmaxf(mx, S[tid * 12 + m]);
        float e[12], sum = 0.f;
        for (int m = 0; m < 12; m++) { e[m] = expf(S[tid * 12 + m] - mx); sum += e[m]; }
        float inv = 1.f / sum;
        for (int m = 0; m < 12; m++) S[tid * 12 + m] = e[m] * inv;
    }
    __syncthreads();
    for (int i = tid; i < 12 * 512; i += 128) {
        int l = i >> 9, d = i & 511;
        float o = 0.f;
        #pragma unroll
        for (int m = 0; m < 12; m++) o += S[l * 12 + m] * v[m * 512 + d];
        g_ao[(size_t)(b * 12 + l) * 512 + d] = o;
    }
}

// =======================================================================
// bov[i] = sum_e cross_out_w[i,e]*cbv[e] + cross_out_b[i]
// =======================================================================
__global__ void bov_kernel(const float* __restrict__ cow,
                           const float* __restrict__ cib,
                           const float* __restrict__ cob)
{
    int i = threadIdx.x;
    const float* cbv = cib + 1024;
    float s = cob[i];
    for (int e = 0; e < 512; e++) s += cow[i * 512 + e] * cbv[e];
    g_bov[i] = s;
}

// fp32 -> fp16 bulk convert (n multiple of 4)
__global__ void f2h_kernel(const float* __restrict__ in, __half* __restrict__ out, size_t n)
{
    size_t i = ((size_t)blockIdx.x * blockDim.x + threadIdx.x) * 4;
    if (i >= n) return;
    float4 v = *(const float4*)(in + i);
    __half2* o = (__half2*)(out + i);
    o[0] = __floats2half2_rn(v.x, v.y);
    o[1] = __floats2half2_rn(v.z, v.w);
}

// =======================================================================
// Fused cross-attention per class:
//   S[192x96] = qkh(rows b0*12..+192) @ text_c^T        (fp16 WMMA, scale pre-folded)
//   softmax over m (12, stride 8 in col idx), sum over l -> w[16x96]
//   rc[16x512] = (w/96) @ text_c                        (fp16 WMMA)
// grid (4 b-chunks, 1000 classes), 256 threads, 196608 B dyn smem.
// =======================================================================
__global__ void attn_cls_kernel()
{
    extern __shared__ char smc[];
    __half* th  = (__half*)smc;                              // 96*512 half = 98304 B
    __half* aq  = (__half*)(smc + 98304);                    // 192*64 half = 24576 B (reused for w)
    float*  Ss  = (float*)(smc + 98304 + 24576);             // 192*96 f32 = 73728 B (reused as stage)
    const int tid  = threadIdx.x;
    const int warp = tid >> 5;
    const int c    = blockIdx.y;
    const int b0   = blockIdx.x * 16;
    const int r0   = b0 * 12;

    // text tile -> smem
    {
        const float4* src = (const float4*)(g_texth + (size_t)c * (96 * 512));
        float4* dst = (float4*)th;
        for (int i = tid; i < 96 * 512 / 8; i += 256) dst[i] = src[i];
    }

    wmma::fragment<wmma::accumulator, 16, 16, 16, float> acc[3][3];
    #pragma unroll
    for (int i = 0; i < 3; i++)
        #pragma unroll
        for (int j = 0; j < 3; j++) wmma::fill_fragment(acc[i][j], 0.f);

    const int wr = warp >> 1, wc = warp & 1;

    for (int kk = 0; kk < 512; kk += 64) {
        for (int i = tid; i < 192 * 8; i += 256) {
            int r = i >> 3, v = i & 7;
            ((float4*)(aq + r * 64))[v] =
                ((const float4*)(g_qkh + (size_t)(r0 + r) * 512 + kk))[v];
        }
        __syncthreads();
        #pragma unroll
        for (int ks = 0; ks < 4; ks++) {
            wmma::fragment<wmma::matrix_a, 16, 16, 16, __half, wmma::row_major> af[3];
            #pragma unroll
            for (int i = 0; i < 3; i++)
                wmma::load_matrix_sync(af[i], aq + ((wr * 3 + i) * 16) * 64 + ks * 16, 64);
            #pragma unroll
            for (int j = 0; j < 3; j++) {
                wmma::fragment<wmma::matrix_b, 16, 16, 16, __half, wmma::col_major> bf;
                wmma::load_matrix_sync(bf, th + ((wc * 3 + j) * 16) * 512 + kk + ks * 16, 512);
                #pragma unroll
                for (int i = 0; i < 3; i++) wmma::mma_sync(acc[i][j], af[i], bf, acc[i][j]);
            }
        }
        __syncthreads();
    }
    #pragma unroll
    for (int i = 0; i < 3; i++)
        #pragma unroll
        for (int j = 0; j < 3; j++)
            wmma::store_matrix_sync(Ss + ((wr * 3 + i) * 16) * 96 + (wc * 3 + j) * 16,
                                    acc[i][j], 96, wmma::mem_row_major);
    __syncthreads();

    // softmax over m (per l,t), sum over l, /96, write half
    __half* wsm = aq;
    if (tid < 128) {
        int bl = tid >> 3, t = tid & 7;
        float wacc[12];
        #pragma unroll
        for (int m = 0; m < 12; m++) wacc[m] = 0.f;
        for (int l = 0; l < 12; l++) {
            int base = (bl * 12 + l) * 96 + t;
            float vals[12], mx = -1e30f;
            #pragma unroll
            for (int m = 0; m < 12; m++) { vals[m] = Ss[base + m * 8]; mx = fmaxf(mx, vals[m]); }
            float sum = 0.f;
            #pragma unroll
            for (int m = 0; m < 12; m++) { vals[m] = __expf(vals[m] - mx); sum += vals[m]; }
            float inv = 1.f / sum;
            #pragma unroll
            for (int m = 0; m < 12; m++) wacc[m] += vals[m] * inv;
        }
        #pragma unroll
        for (int m = 0; m < 12; m++)
            wsm[bl * 96 + m * 8 + t] = __float2half(wacc[m] * (1.f / 96.f));
    }
    __syncthreads();

    // rc = w @ text_c  -> stage [16x512] f32
    {
        wmma::fragment<wmma::accumulator, 16, 16, 16, float> rca[4];
        #pragma unroll
        for (int j = 0; j < 4; j++) wmma::fill_fragment(rca[j], 0.f);
        #pragma unroll
        for (int kt = 0; kt < 6; kt++) {
            wmma::fragment<wmma::matrix_a, 16, 16, 16, __half, wmma::row_major> af;
            wmma::load_matrix_sync(af, wsm + kt * 16, 96);
            #pragma unroll
            for (int j = 0; j < 4; j++) {
                wmma::fragment<wmma::matrix_b, 16, 16, 16, __half, wmma::row_major> bf;
                wmma::load_matrix_sync(bf, th + (kt * 16) * 512 + (warp * 4 + j) * 16, 512);
                wmma::mma_sync(rca[j], af, bf, rca[j]);
            }
        }
        #pragma unroll
        for (int j = 0; j < 4; j++)
            wmma::store_matrix_sync(Ss + (warp * 4 + j) * 16, rca[j], 512, wmma::mem_row_major);
    }
    __syncthreads();

    for (int i = tid; i < 16 * 512; i += 256) {
        int bl = i >> 9, d = i & 511;
        g_rch[((size_t)(b0 + bl) * 1000 + c) * 512 + d] = __float2half(Ss[i]);
    }
}

// =======================================================================
// txt = rc @ Wov^T  (bias deferred to consumers). M=64000,N=512,K=512.
// grid (4 col tiles, 500 row tiles), 256 threads.
// =======================================================================
__global__ void txt_gemm_kernel()
{
    __shared__ __half As[128 * 64];
    __shared__ __half Bs[128 * 64];
    const int tid = threadIdx.x, warp = tid >> 5;
    const size_t m0 = (size_t)blockIdx.y * 128;
    const int n0 = blockIdx.x * 128;
    const int wr = warp >> 1, wc = warp & 1;
    wmma::fragment<wmma::accumulator, 16, 16, 16, float> acc[2][4];
    #pragma unroll
    for (int i = 0; i < 2; i++)
        #pragma unroll
        for (int j = 0; j < 4; j++) wmma::fill_fragment(acc[i][j], 0.f);

    for (int kk = 0; kk < 512; kk += 64) {
        for (int i = tid; i < 128 * 8; i += 256) {
            int r = i >> 3, v = i & 7;
            ((float4*)(As + r * 64))[v] = ((const float4*)(g_rch + (m0 + r) * 512 + kk))[v];
        }
        for (int i = tid; i < 128 * 8; i += 256) {
            int n = i >> 3, v = i & 7;
            ((float4*)(Bs + n * 64))[v] = ((const float4*)(g_Wovh + (size_t)(n0 + n) * 512 + kk))[v];
        }
        __syncthreads();
        #pragma unroll
        for (int ks = 0; ks < 4; ks++) {
            wmma::fragment<wmma::matrix_a, 16, 16, 16, __half, wmma::row_major> af[2];
            #pragma unroll
            for (int i = 0; i < 2; i++)
                wmma::load_matrix_sync(af[i], As + ((wr * 2 + i) * 16) * 64 + ks * 16, 64);
            #pragma unroll
            for (int j = 0; j < 4; j++) {
                wmma::fragment<wmma::matrix_b, 16, 16, 16, __half, wmma::col_major> bf;
                wmma::load_matrix_sync(bf, Bs + ((wc * 4 + j) * 16) * 64 + ks * 16, 64);
                #pragma unroll
                for (int i = 0; i < 2; i++) wmma::mma_sync(acc[i][j], af[i], bf, acc[i][j]);
            }
        }
        __syncthreads();
    }
    #pragma unroll
    for (int i = 0; i < 2; i++)
        #pragma unroll
        for (int j = 0; j < 4; j++)
            wmma::store_matrix_sync(g_txt + (m0 + (wr * 2 + i) * 16) * 512 + n0 + (wc * 4 + j) * 16,
                                    acc[i][j], 512, wmma::mem_row_major);
}

// partial column-norms: part[chunk][b][d] = sum over 125 classes of (txt+bov)^2
__global__ void colnorm_partial()
{
    const int b = blockIdx.y, chunk = blockIdx.x, d = threadIdx.x;
    const float bv = g_bov[d];
    float acc = 0.f;
    const int cs = chunk * 125;
    for (int c = cs; c < cs + 125; c++) {
        float v = g_txt[((size_t)b * 1000 + c) * 512 + d] + bv;
        acc += v * v;
    }
    g_part[(size_t)(chunk * 64 + b) * 512 + d] = acc;
}

// h[b,d] = (img[d]/||img_b||) / sqrt(sum_c txt^2)
__global__ void make_h_kernel()
{
    __shared__ float red[512];
    const int b = blockIdx.x, d = threadIdx.x;
    float nrm2 = 0.f;
    #pragma unroll
    for (int p = 0; p < 8; p++) nrm2 += g_part[(size_t)(p * 64 + b) * 512 + d];
    float iv = g_xs[(size_t)(b * 12 + 11) * 512 + d];
    red[d] = iv * iv;
    __syncthreads();
    for (int s = 256; s > 0; s >>= 1) {
        if (d < s) red[d] += red[d + s];
        __syncthreads();
    }
    g_h[b * 512 + d] = iv * rsqrtf(red[0]) * rsqrtf(nrm2);
}

// logits[b,c] = exp(ls) * sum_d h[b,d]*(txt[b,c,d]+bov[d])
__global__ void logits_kernel(const float* __restrict__ ls, float* __restrict__ out)
{
    __shared__ float hs[512], bs[512];
    const int b = blockIdx.y;
    const int tid = threadIdx.x, warp = tid >> 5, lane = tid & 31;
    const int c = blockIdx.x * 8 + warp;
    for (int i = tid; i < 512; i += 256) { hs[i] = g_h[b * 512 + i]; bs[i] = g_bov[i]; }
    __syncthreads();
    const float* row = g_txt + ((size_t)b * 1000 + c) * 512;
    float acc = 0.f;
    for (int kk = lane; kk < 512; kk += 32) acc += hs[kk] * (row[kk] + bs[kk]);
    #pragma unroll
    for (int off = 16; off > 0; off >>= 1) acc += __shfl_xor_sync(0xffffffff, acc, off);
    if (lane == 0) out[(size_t)b * 1000 + c] = expf(ls[0]) * acc;
}

// =======================================================================
extern "C" void kernel_launch(void* const* d_in, const int* in_sizes, int n_in,
                              void* d_out, int out_size)
{
    const float* x   = (const float*)d_in[0];
    const float* txt = (const float*)d_in[1];
    const float* siw = (const float*)d_in[2];
    const float* sib = (const float*)d_in[3];
    const float* sow = (const float*)d_in[4];
    const float* sob = (const float*)d_in[5];
    const float* ciw = (const float*)d_in[6];
    const float* cib = (const float*)d_in[7];
    const float* cow = (const float*)d_in[8];
    const float* cob = (const float*)d_in[9];
    const float* ls  = (const float*)d_in[10];
    float* out = (float*)d_out;

    float *p_qkv, *p_ao, *p_xs, *p_q2;
    __half *p_qkh, *p_texth, *p_Wovh;
    cudaGetSymbolAddress((void**)&p_qkv,  g_qkv);
    cudaGetSymbolAddress((void**)&p_ao,   g_ao);
    cudaGetSymbolAddress((void**)&p_xs,   g_xs);
    cudaGetSymbolAddress((void**)&p_q2,   g_q2);
    cudaGetSymbolAddress((void**)&p_qkh,  g_qkh);
    cudaGetSymbolAddress((void**)&p_texth, g_texth);
    cudaGetSymbolAddress((void**)&p_Wovh, g_Wovh);

    cudaFuncSetAttribute(self_attn_kernel, cudaFuncAttributeMaxDynamicSharedMemorySize, 74304);
    cudaFuncSetAttribute(attn_cls_kernel,  cudaFuncAttributeMaxDynamicSharedMemorySize, 196608);

    // prologue (fp32 SIMT)
    gemm_simt<<<dim3(24, 12), 256>>>(x, 512, siw, 1, 512, sib, 1.f, p_qkv, nullptr, 1536, 512);
    self_attn_kernel<<<64, 128, 74304>>>();
    gemm_simt<<<dim3(8, 12), 256>>>(p_ao, 512, sow, 1, 512, sob, 1.f, p_xs, nullptr, 512, 512);
    gemm_simt<<<dim3(8, 12), 256>>>(p_xs, 512, ciw, 1, 512, cib, 1.f, p_q2, nullptr, 512, 512);
    // qk = q2 @ cWk, pre-scaled, fp16
    gemm_simt<<<dim3(8, 12), 256>>>(p_q2, 512, ciw + 512 * 512, 512, 1, nullptr, ATTN_SCALE,
                                    nullptr, p_qkh, 512, 512);
    // Wov = cross_out_w @ cWv (fp16), bov
    gemm_simt<<<dim3(8, 8), 256>>>(cow, 512, ciw + 1024 * 512, 512, 1, nullptr, 1.f,
                                   nullptr, p_Wovh, 512, 512);
    bov_kernel<<<1, 512>>>(cow, cib, cob);

    // text -> fp16
    f2h_kernel<<<48000, 256>>>(txt, p_texth, (size_t)1000 * 96 * 512);

    // fused cross-attention + softmax + layer-sum + context
    attn_cls_kernel<<<dim3(4, 1000), 256, 196608>>>();

    // projection GEMM
    txt_gemm_kernel<<<dim3(4, 500), 256>>>();

    // norms + logits
    colnorm_partial<<<dim3(8, 64), 512>>>();
    make_h_kernel<<<64, 512>>>();
    logits_kernel<<<dim3(125, 64), 256>>>(ls, out);
}

// round 3
// speedup vs baseline: 3.5985x; 3.5985x over previous
#include <cuda_runtime.h>
#include <cuda_fp16.h>
#include <mma.h>

using namespace nvcuda;

#define ATTN_SCALE 0.044194173824159216f  // 1/sqrt(512)

// padded leading dims (conflict-free WMMA smem)
#define TH_LD 520   // text tile rows (halves)
#define AQ_LD 72    // aq rows (halves)
#define SS_LD 100   // S staging rows (floats)

// ---------------- static device scratch ----------------
__device__ __align__(16) float  g_qkv [768 * 1536];
__device__ __align__(16) float  g_ao  [768 * 512];
__device__ __align__(16) float  g_xs  [768 * 512];
__device__ __align__(16) float  g_W2  [512 * 512];
__device__ __align__(16) float  g_bqk [512];
__device__ __align__(16) __half g_qkh [768 * 512];
__device__ __align__(16) __half g_texth[(size_t)1000 * 96 * 512];
__device__ __align__(16) __half g_Wovh[512 * 512];
__device__ __align__(16) float  g_bov [512];
__device__ __align__(16) __half g_rch [(size_t)64 * 1000 * 512];
__device__ __align__(16) float  g_txt [(size_t)64 * 1000 * 512];
__device__ __align__(16) float  g_part[8 * 64 * 512];
__device__ __align__(16) float  g_h   [64 * 512];

// =======================================================================
// fp32 GEMM, 64x64 tile, k-chunk 32, register-pipelined, conflict-free.
// C[m,n] = scale * sum_k A(m,k)*B(k,n) + bias[n]
// A(m,k) at A[m*as_m + k*as_k]; B(k,n) at B[k*bs_k + n*bs_n].
// =======================================================================
__global__ void gemm_f32(const float* __restrict__ A, int as_m, int as_k,
                         const float* __restrict__ B, int bs_k, int bs_n,
                         const float* __restrict__ bias, float scale,
                         float* __restrict__ Cf, __half* __restrict__ Ch,
                         int N, int K)
{
    __shared__ float Asm[32][65];
    __shared__ float Bsm[32][65];
    const int tid = threadIdx.x;
    const int tx = tid & 15, ty = tid >> 4;
    const int m0 = blockIdx.y * 64, n0 = blockIdx.x * 64;
    float ra[8], rb[8];
    float acc[4][4] = {};

    const int nk = K >> 5;
    // prefetch chunk 0
    #pragma unroll
    for (int i = 0; i < 8; i++) {
        int idx = tid + i * 256; int r, c;
        if (as_k == 1) { r = idx >> 5; c = idx & 31; } else { r = idx & 63; c = idx >> 6; }
        ra[i] = A[(size_t)(m0 + r) * as_m + (size_t)c * as_k];
    }
    #pragma unroll
    for (int i = 0; i < 8; i++) {
        int idx = tid + i * 256; int k, n;
        if (bs_n == 1) { n = idx & 63; k = idx >> 6; } else { n = idx >> 5; k = idx & 31; }
        rb[i] = B[(size_t)k * bs_k + (size_t)(n0 + n) * bs_n];
    }

    for (int kc = 0; kc < nk; kc++) {
        // store regs -> smem
        #pragma unroll
        for (int i = 0; i < 8; i++) {
            int idx = tid + i * 256; int r, c;
            if (as_k == 1) { r = idx >> 5; c = idx & 31; } else { r = idx & 63; c = idx >> 6; }
            Asm[c][r] = ra[i];
        }
        #pragma unroll
        for (int i = 0; i < 8; i++) {
            int idx = tid + i * 256; int k, n;
            if (bs_n == 1) { n = idx & 63; k = idx >> 6; } else { n = idx >> 5; k = idx & 31; }
            Bsm[k][n] = rb[i];
        }
        __syncthreads();
        if (kc + 1 < nk) {
            int kk = (kc + 1) << 5;
            #pragma unroll
            for (int i = 0; i < 8; i++) {
                int idx = tid + i * 256; int r, c;
                if (as_k == 1) { r = idx >> 5; c = idx & 31; } else { r = idx & 63; c = idx >> 6; }
                ra[i] = A[(size_t)(m0 + r) * as_m + (size_t)(kk + c) * as_k];
            }
            #pragma unroll
            for (int i = 0; i < 8; i++) {
                int idx = tid + i * 256; int k, n;
                if (bs_n == 1) { n = idx & 63; k = idx >> 6; } else { n = idx >> 5; k = idx & 31; }
                rb[i] = B[(size_t)(kk + k) * bs_k + (size_t)(n0 + n) * bs_n];
            }
        }
        #pragma unroll
        for (int k = 0; k < 32; k++) {
            float av[4], bv[4];
            #pragma unroll
            for (int i = 0; i < 4; i++) av[i] = Asm[k][ty * 4 + i];
            #pragma unroll
            for (int j = 0; j < 4; j++) bv[j] = Bsm[k][tx * 4 + j];
            #pragma unroll
            for (int i = 0; i < 4; i++)
                #pragma unroll
                for (int j = 0; j < 4; j++) acc[i][j] += av[i] * bv[j];
        }
        __syncthreads();
    }
    #pragma unroll
    for (int i = 0; i < 4; i++) {
        size_t m = m0 + ty * 4 + i;
        #pragma unroll
        for (int j = 0; j < 4; j++) {
            int n = n0 + tx * 4 + j;
            float v = acc[i][j] * scale + (bias ? bias[n] : 0.f);
            if (Cf) Cf[m * N + n] = v;
            if (Ch) Ch[m * N + n] = __float2half(v);
        }
    }
}

// =======================================================================
__global__ void self_attn_kernel()
{
    extern __shared__ float sh[];
    float* q = sh;
    float* k = q + 12 * 512;
    float* v = k + 12 * 512;
    float* S = v + 12 * 512;
    const int b = blockIdx.x, tid = threadIdx.x;
    for (int i = tid; i < 12 * 512; i += 128) {
        int l = i >> 9, d = i & 511;
        const float* row = g_qkv + (size_t)(l * 64 + b) * 1536;
        q[i] = row[d]; k[i] = row[512 + d]; v[i] = row[1024 + d];
    }
    __syncthreads();
    for (int i = tid; i < 144; i += 128) {
        int l = i / 12, m = i - l * 12;
        const float* qp = q + l * 512;
        const float* kp = k + m * 512;
        float s = 0.f;
        for (int e = 0; e < 512; e++) s += qp[e] * kp[e];
        S[i] = s * ATTN_SCALE;
    }
    __syncthreads();
    if (tid < 12) {
        float mx = -1e30f;
        for (int m = 0; m < 12; m++) mx = fmaxf(mx, S[tid * 12 + m]);
        float e[12], sum = 0.f;
        for (int m = 0; m < 12; m++) { e[m] = expf(S[tid * 12 + m] - mx); sum += e[m]; }
        float inv = 1.f / sum;
        for (int m = 0; m < 12; m++) S[tid * 12 + m] = e[m] * inv;
    }
    __syncthreads();
    for (int i = tid; i < 12 * 512; i += 128) {
        int l = i >> 9, d = i & 511;
        float o = 0.f;
        #pragma unroll
        for (int m = 0; m < 12; m++) o += S[l * 12 + m] * v[m * 512 + d];
        g_ao[(size_t)(b * 12 + l) * 512 + d] = o;
    }
}

// bqk[d] = scale * sum_e cbq[e]*cWk[e,d]
__global__ void bqk_kernel(const float* __restrict__ ciw, const float* __restrict__ cib)
{
    int d = threadIdx.x;
    const float* cWk = ciw + 512 * 512;
    float s = 0.f;
    for (int e = 0; e < 512; e++) s += cib[e] * cWk[e * 512 + d];
    g_bqk[d] = s * ATTN_SCALE;
}

// bov[i] = sum_e cow[i,e]*cbv[e] + cob[i]
__global__ void bov_kernel(const float* __restrict__ cow,
                           const float* __restrict__ cib,
                           const float* __restrict__ cob)
{
    int i = threadIdx.x;
    const float* cbv = cib + 1024;
    float s = cob[i];
    for (int e = 0; e < 512; e++) s += cow[i * 512 + e] * cbv[e];
    g_bov[i] = s;
}

__global__ void f2h_kernel(const float* __restrict__ in, __half* __restrict__ out, size_t n)
{
    size_t i = ((size_t)blockIdx.x * blockDim.x + threadIdx.x) * 4;
    if (i >= n) return;
    float4 v = *(const float4*)(in + i);
    __half2* o = (__half2*)(out + i);
    o[0] = __floats2half2_rn(v.x, v.y);
    o[1] = __floats2half2_rn(v.z, v.w);
}

// =======================================================================
// Fused cross-attention per class (padded smem, register-pipelined aq).
// grid (4 b-chunks, 1000 classes), 256 threads, dyn smem 204288 B.
// =======================================================================
__global__ void attn_cls_kernel()
{
    extern __shared__ char smc[];
    __half* th = (__half*)smc;                                   // 96 x TH_LD
    __half* aq = (__half*)(smc + 96 * TH_LD * 2);                // 192 x AQ_LD
    float*  Ss = (float*)(smc + 96 * TH_LD * 2 + 192 * AQ_LD * 2); // 192 x SS_LD
    const int tid  = threadIdx.x;
    const int warp = tid >> 5;
    const int c    = blockIdx.y;
    const int b0   = blockIdx.x * 16;
    const int r0   = b0 * 12;
    const __half* qbase = g_qkh + (size_t)r0 * 512;

    // prefetch aq chunk 0 into regs
    uint4 ra[6];
    #pragma unroll
    for (int i = 0; i < 6; i++) {
        int f = tid + i * 256, r = f >> 3, v = f & 7;
        ra[i] = ((const uint4*)(qbase + (size_t)r * 512))[v];
    }
    // text tile -> smem (padded rows)
    {
        const uint4* src = (const uint4*)(g_texth + (size_t)c * (96 * 512));
        for (int i = tid; i < 96 * 64; i += 256) {
            int row = i >> 6, v = i & 63;
            *((uint4*)(th + row * TH_LD) + v) = src[i];
        }
    }

    wmma::fragment<wmma::accumulator, 16, 16, 16, float> acc[3][3];
    #pragma unroll
    for (int i = 0; i < 3; i++)
        #pragma unroll
        for (int j = 0; j < 3; j++) wmma::fill_fragment(acc[i][j], 0.f);
    const int wr = warp >> 1, wc = warp & 1;

    __syncthreads();  // text ready

    for (int kc = 0; kc < 8; kc++) {
        #pragma unroll
        for (int i = 0; i < 6; i++) {
            int f = tid + i * 256, r = f >> 3, v = f & 7;
            *((uint4*)(aq + r * AQ_LD) + v) = ra[i];
        }
        __syncthreads();
        if (kc < 7) {
            #pragma unroll
            for (int i = 0; i < 6; i++) {
                int f = tid + i * 256, r = f >> 3, v = f & 7;
                ra[i] = ((const uint4*)(qbase + (size_t)r * 512 + (kc + 1) * 64))[v];
            }
        }
        #pragma unroll
        for (int ks = 0; ks < 4; ks++) {
            wmma::fragment<wmma::matrix_a, 16, 16, 16, __half, wmma::row_major> af[3];
            #pragma unroll
            for (int i = 0; i < 3; i++)
                wmma::load_matrix_sync(af[i], aq + ((wr * 3 + i) * 16) * AQ_LD + ks * 16, AQ_LD);
            #pragma unroll
            for (int j = 0; j < 3; j++) {
                wmma::fragment<wmma::matrix_b, 16, 16, 16, __half, wmma::col_major> bf;
                wmma::load_matrix_sync(bf, th + ((wc * 3 + j) * 16) * TH_LD + kc * 64 + ks * 16, TH_LD);
                #pragma unroll
                for (int i = 0; i < 3; i++) wmma::mma_sync(acc[i][j], af[i], bf, acc[i][j]);
            }
        }
        __syncthreads();
    }
    #pragma unroll
    for (int i = 0; i < 3; i++)
        #pragma unroll
        for (int j = 0; j < 3; j++)
            wmma::store_matrix_sync(Ss + ((wr * 3 + i) * 16) * SS_LD + (wc * 3 + j) * 16,
                                    acc[i][j], SS_LD, wmma::mem_row_major);
    __syncthreads();

    // softmax over m, sum over l, /96 -> wsm (reuse aq)
    __half* wsm = aq;
    if (tid < 128) {
        int bl = tid >> 3, t = tid & 7;
        float wacc[12];
        #pragma unroll
        for (int m = 0; m < 12; m++) wacc[m] = 0.f;
        for (int l = 0; l < 12; l++) {
            int base = (bl * 12 + l) * SS_LD + t;
            float vals[12], mx = -1e30f;
            #pragma unroll
            for (int m = 0; m < 12; m++) { vals[m] = Ss[base + m * 8]; mx = fmaxf(mx, vals[m]); }
            float sum = 0.f;
            #pragma unroll
            for (int m = 0; m < 12; m++) { vals[m] = __expf(vals[m] - mx); sum += vals[m]; }
            float inv = 1.f / sum;
            #pragma unroll
            for (int m = 0; m < 12; m++) wacc[m] += vals[m] * inv;
        }
        #pragma unroll
        for (int m = 0; m < 12; m++)
            wsm[bl * 96 + m * 8 + t] = __float2half(wacc[m] * (1.f / 96.f));
    }
    __syncthreads();

    // rc = w @ text -> stage [16 x 520] f32 in Ss
    {
        wmma::fragment<wmma::accumulator, 16, 16, 16, float> rca[4];
        #pragma unroll
        for (int j = 0; j < 4; j++) wmma::fill_fragment(rca[j], 0.f);
        #pragma unroll
        for (int kt = 0; kt < 6; kt++) {
            wmma::fragment<wmma::matrix_a, 16, 16, 16, __half, wmma::row_major> af;
            wmma::load_matrix_sync(af, wsm + kt * 16, 96);
            #pragma unroll
            for (int j = 0; j < 4; j++) {
                wmma::fragment<wmma::matrix_b, 16, 16, 16, __half, wmma::row_major> bf;
                wmma::load_matrix_sync(bf, th + (kt * 16) * TH_LD + (warp * 4 + j) * 16, TH_LD);
                wmma::mma_sync(rca[j], af, bf, rca[j]);
            }
        }
        #pragma unroll
        for (int j = 0; j < 4; j++)
            wmma::store_matrix_sync(Ss + (warp * 4 + j) * 16, rca[j], TH_LD, wmma::mem_row_major);
    }
    __syncthreads();

    for (int i = tid; i < 16 * 512; i += 256) {
        int bl = i >> 9, d = i & 511;
        g_rch[((size_t)(b0 + bl) * 1000 + c) * 512 + d] = __float2half(Ss[bl * TH_LD + d]);
    }
}

// =======================================================================
// txt = rc @ Wov^T  (padded smem, register-pipelined). M=64000,N=512,K=512.
// grid (4, 500), 256 threads.
// =======================================================================
__global__ void txt_gemm_kernel()
{
    __shared__ __half As[128 * 72];
    __shared__ __half Bs[128 * 72];
    const int tid = threadIdx.x, warp = tid >> 5;
    const size_t m0 = (size_t)blockIdx.y * 128;
    const int n0 = blockIdx.x * 128;
    const int wr = warp >> 1, wc = warp & 1;
    uint4 ra[4], rb[4];
    wmma::fragment<wmma::accumulator, 16, 16, 16, float> acc[2][4];
    #pragma unroll
    for (int i = 0; i < 2; i++)
        #pragma unroll
        for (int j = 0; j < 4; j++) wmma::fill_fragment(acc[i][j], 0.f);

    #pragma unroll
    for (int i = 0; i < 4; i++) {
        int f = tid + i * 256, r = f >> 3, v = f & 7;
        ra[i] = ((const uint4*)(g_rch + (m0 + r) * 512))[v];
        rb[i] = ((const uint4*)(g_Wovh + (size_t)(n0 + r) * 512))[v];
    }

    for (int kc = 0; kc < 8; kc++) {
        #pragma unroll
        for (int i = 0; i < 4; i++) {
            int f = tid + i * 256, r = f >> 3, v = f & 7;
            *((uint4*)(As + r * 72) + v) = ra[i];
            *((uint4*)(Bs + r * 72) + v) = rb[i];
        }
        __syncthreads();
        if (kc < 7) {
            int kk = (kc + 1) * 64;
            #pragma unroll
            for (int i = 0; i < 4; i++) {
                int f = tid + i * 256, r = f >> 3, v = f & 7;
                ra[i] = ((const uint4*)(g_rch + (m0 + r) * 512 + kk))[v];
                rb[i] = ((const uint4*)(g_Wovh + (size_t)(n0 + r) * 512 + kk))[v];
            }
        }
        #pragma unroll
        for (int ks = 0; ks < 4; ks++) {
            wmma::fragment<wmma::matrix_a, 16, 16, 16, __half, wmma::row_major> af[2];
            #pragma unroll
            for (int i = 0; i < 2; i++)
                wmma::load_matrix_sync(af[i], As + ((wr * 2 + i) * 16) * 72 + ks * 16, 72);
            #pragma unroll
            for (int j = 0; j < 4; j++) {
                wmma::fragment<wmma::matrix_b, 16, 16, 16, __half, wmma::col_major> bf;
                wmma::load_matrix_sync(bf, Bs + ((wc * 4 + j) * 16) * 72 + ks * 16, 72);
                #pragma unroll
                for (int i = 0; i < 2; i++) wmma::mma_sync(acc[i][j], af[i], bf, acc[i][j]);
            }
        }
        __syncthreads();
    }
    #pragma unroll
    for (int i = 0; i < 2; i++)
        #pragma unroll
        for (int j = 0; j < 4; j++)
            wmma::store_matrix_sync(g_txt + (m0 + (wr * 2 + i) * 16) * 512 + n0 + (wc * 4 + j) * 16,
                                    acc[i][j], 512, wmma::mem_row_major);
}

// partial column-norms over 125-class chunks
__global__ void colnorm_partial()
{
    const int b = blockIdx.y, chunk = blockIdx.x, d = threadIdx.x;
    const float bv = g_bov[d];
    float acc = 0.f;
    const int cs = chunk * 125;
    for (int c = cs; c < cs + 125; c++) {
        float v = g_txt[((size_t)b * 1000 + c) * 512 + d] + bv;
        acc += v * v;
    }
    g_part[(size_t)(chunk * 64 + b) * 512 + d] = acc;
}

__global__ void make_h_kernel()
{
    __shared__ float red[512];
    const int b = blockIdx.x, d = threadIdx.x;
    float nrm2 = 0.f;
    #pragma unroll
    for (int p = 0; p < 8; p++) nrm2 += g_part[(size_t)(p * 64 + b) * 512 + d];
    float iv = g_xs[(size_t)(b * 12 + 11) * 512 + d];
    red[d] = iv * iv;
    __syncthreads();
    for (int s = 256; s > 0; s >>= 1) {
        if (d < s) red[d] += red[d + s];
        __syncthreads();
    }
    g_h[b * 512 + d] = iv * rsqrtf(red[0]) * rsqrtf(nrm2);
}

__global__ void logits_kernel(const float* __restrict__ ls, float* __restrict__ out)
{
    __shared__ float hs[512], bs[512];
    const int b = blockIdx.y;
    const int tid = threadIdx.x, warp = tid >> 5, lane = tid & 31;
    const int c = blockIdx.x * 8 + warp;
    for (int i = tid; i < 512; i += 256) { hs[i] = g_h[b * 512 + i]; bs[i] = g_bov[i]; }
    __syncthreads();
    const float* row = g_txt + ((size_t)b * 1000 + c) * 512;
    float acc = 0.f;
    for (int kk = lane; kk < 512; kk += 32) acc += hs[kk] * (row[kk] + bs[kk]);
    #pragma unroll
    for (int off = 16; off > 0; off >>= 1) acc += __shfl_xor_sync(0xffffffff, acc, off);
    if (lane == 0) out[(size_t)b * 1000 + c] = expf(ls[0]) * acc;
}

// =======================================================================
extern "C" void kernel_launch(void* const* d_in, const int* in_sizes, int n_in,
                              void* d_out, int out_size)
{
    const float* x   = (const float*)d_in[0];
    const float* txt = (const float*)d_in[1];
    const float* siw = (const float*)d_in[2];
    const float* sib = (const float*)d_in[3];
    const float* sow = (const float*)d_in[4];
    const float* sob = (const float*)d_in[5];
    const float* ciw = (const float*)d_in[6];
    const float* cib = (const float*)d_in[7];
    const float* cow = (const float*)d_in[8];
    const float* cob = (const float*)d_in[9];
    const float* ls  = (const float*)d_in[10];
    float* out = (float*)d_out;

    float *p_qkv, *p_ao, *p_xs, *p_W2, *p_bqk;
    __half *p_qkh, *p_texth, *p_Wovh;
    cudaGetSymbolAddress((void**)&p_qkv,   g_qkv);
    cudaGetSymbolAddress((void**)&p_ao,    g_ao);
    cudaGetSymbolAddress((void**)&p_xs,    g_xs);
    cudaGetSymbolAddress((void**)&p_W2,    g_W2);
    cudaGetSymbolAddress((void**)&p_bqk,   g_bqk);
    cudaGetSymbolAddress((void**)&p_qkh,   g_qkh);
    cudaGetSymbolAddress((void**)&p_texth, g_texth);
    cudaGetSymbolAddress((void**)&p_Wovh,  g_Wovh);

    cudaFuncSetAttribute(self_attn_kernel, cudaFuncAttributeMaxDynamicSharedMemorySize, 74304);
    cudaFuncSetAttribute(attn_cls_kernel,  cudaFuncAttributeMaxDynamicSharedMemorySize, 204288);

    // ---- prologue ----
    // qkv = x @ siw^T + sib        (A: m-major k-contig; B: NT)
    gemm_f32<<<dim3(24, 12), 256>>>(x, 512, 1, siw, 1, 512, sib, 1.f, p_qkv, nullptr, 1536, 512);
    // W2 = scale * cWq^T @ cWk     (A: TN; B: NN)
    gemm_f32<<<dim3(8, 8), 256>>>(ciw, 1, 512, ciw + 512 * 512, 512, 1, nullptr, ATTN_SCALE,
                                  p_W2, nullptr, 512, 512);
    // Wov = cow @ cWv              (A: NT-row; B: NN) -> half
    gemm_f32<<<dim3(8, 8), 256>>>(cow, 512, 1, ciw + 1024 * 512, 512, 1, nullptr, 1.f,
                                  nullptr, p_Wovh, 512, 512);
    bqk_kernel<<<1, 512>>>(ciw, cib);
    bov_kernel<<<1, 512>>>(cow, cib, cob);

    self_attn_kernel<<<64, 128, 74304>>>();
    // xs = ao @ sow^T + sob
    gemm_f32<<<dim3(8, 12), 256>>>(p_ao, 512, 1, sow, 1, 512, sob, 1.f, p_xs, nullptr, 512, 512);
    // qk = xs @ W2 + bqk  (pre-scaled) -> half
    gemm_f32<<<dim3(8, 12), 256>>>(p_xs, 512, 1, p_W2, 512, 1, p_bqk, 1.f,
                                   nullptr, p_qkh, 512, 512);

    // text -> fp16
    f2h_kernel<<<48000, 256>>>(txt, p_texth, (size_t)1000 * 96 * 512);

    // fused cross-attention
    attn_cls_kernel<<<dim3(4, 1000), 256, 204288>>>();

    // projection
    txt_gemm_kernel<<<dim3(4, 500), 256>>>();

    // norms + logits
    colnorm_partial<<<dim3(8, 64), 512>>>();
    make_h_kernel<<<64, 512>>>();
    logits_kernel<<<dim3(125, 64), 256>>>(ls, out);
}

// round 6
// speedup vs baseline: 4.3402x; 1.2061x over previous
#include <cuda_runtime.h>
#include <cuda_fp16.h>
#include <cstdint>
#include <mma.h>

using namespace nvcuda;

#define ATTN_SCALE 0.044194173824159216f  // 1/sqrt(512)
#define TH_LD 520   // text tile leading dim (halves)
#define AQ_LD 72    // aq leading dim (halves)
#define SS_LD 100   // S staging leading dim (floats)

// ---------------- static device scratch ----------------
__device__ __align__(16) float  g_qkv [768 * 1536];
__device__ __align__(16) float  g_ao  [768 * 512];
__device__ __align__(16) float  g_xs  [768 * 512];
__device__ __align__(16) float  g_W2  [512 * 512];
__device__ __align__(16) float  g_bqk [512];
__device__ __align__(16) __half g_qkh [768 * 512];
__device__ __align__(16) __half g_texth[(size_t)1000 * 96 * 512];
__device__ __align__(16) __half g_Wovh[512 * 512];
__device__ __align__(16) float  g_bov [512];
__device__ __align__(16) __half g_rch [(size_t)64 * 1000 * 512];
__device__ __align__(16) float  g_txt [(size_t)64 * 1000 * 512];
__device__ __align__(16) float  g_part[8 * 64 * 512];
__device__ __align__(16) float  g_h   [64 * 512];

// =======================================================================
// fp32 GEMM (prologue), 64x64 tile, k-chunk 32, register-pipelined.
// C[m,n] = scale * sum_k A(m,k)*B(k,n) + bias[n]
// =======================================================================
__global__ void gemm_f32(const float* __restrict__ A, int as_m, int as_k,
                         const float* __restrict__ B, int bs_k, int bs_n,
                         const float* __restrict__ bias, float scale,
                         float* __restrict__ Cf, __half* __restrict__ Ch,
                         int N, int K)
{
    __shared__ float Asm[32][65];
    __shared__ float Bsm[32][65];
    const int tid = threadIdx.x;
    const int tx = tid & 15, ty = tid >> 4;
    const int m0 = blockIdx.y * 64, n0 = blockIdx.x * 64;
    float ra[8], rb[8];
    float acc[4][4] = {};
    const int nk = K >> 5;

    #pragma unroll
    for (int i = 0; i < 8; i++) {
        int idx = tid + i * 256; int r, c;
        if (as_k == 1) { r = idx >> 5; c = idx & 31; } else { r = idx & 63; c = idx >> 6; }
        ra[i] = A[(size_t)(m0 + r) * as_m + (size_t)c * as_k];
    }
    #pragma unroll
    for (int i = 0; i < 8; i++) {
        int idx = tid + i * 256; int k, n;
        if (bs_n == 1) { n = idx & 63; k = idx >> 6; } else { n = idx >> 5; k = idx & 31; }
        rb[i] = B[(size_t)k * bs_k + (size_t)(n0 + n) * bs_n];
    }
    for (int kc = 0; kc < nk; kc++) {
        #pragma unroll
        for (int i = 0; i < 8; i++) {
            int idx = tid + i * 256; int r, c;
            if (as_k == 1) { r = idx >> 5; c = idx & 31; } else { r = idx & 63; c = idx >> 6; }
            Asm[c][r] = ra[i];
        }
        #pragma unroll
        for (int i = 0; i < 8; i++) {
            int idx = tid + i * 256; int k, n;
            if (bs_n == 1) { n = idx & 63; k = idx >> 6; } else { n = idx >> 5; k = idx & 31; }
            Bsm[k][n] = rb[i];
        }
        __syncthreads();
        if (kc + 1 < nk) {
            int kk = (kc + 1) << 5;
            #pragma unroll
            for (int i = 0; i < 8; i++) {
                int idx = tid + i * 256; int r, c;
                if (as_k == 1) { r = idx >> 5; c = idx & 31; } else { r = idx & 63; c = idx >> 6; }
                ra[i] = A[(size_t)(m0 + r) * as_m + (size_t)(kk + c) * as_k];
            }
            #pragma unroll
            for (int i = 0; i < 8; i++) {
                int idx = tid + i * 256; int k, n;
                if (bs_n == 1) { n = idx & 63; k = idx >> 6; } else { n = idx >> 5; k = idx & 31; }
                rb[i] = B[(size_t)(kk + k) * bs_k + (size_t)(n0 + n) * bs_n];
            }
        }
        #pragma unroll
        for (int k = 0; k < 32; k++) {
            float av[4], bv[4];
            #pragma unroll
            for (int i = 0; i < 4; i++) av[i] = Asm[k][ty * 4 + i];
            #pragma unroll
            for (int j = 0; j < 4; j++) bv[j] = Bsm[k][tx * 4 + j];
            #pragma unroll
            for (int i = 0; i < 4; i++)
                #pragma unroll
                for (int j = 0; j < 4; j++) acc[i][j] += av[i] * bv[j];
        }
        __syncthreads();
    }
    #pragma unroll
    for (int i = 0; i < 4; i++) {
        size_t m = m0 + ty * 4 + i;
        #pragma unroll
        for (int j = 0; j < 4; j++) {
            int n = n0 + tx * 4 + j;
            float v = acc[i][j] * scale + (bias ? bias[n] : 0.f);
            if (Cf) Cf[m * N + n] = v;
            if (Ch) Ch[m * N + n] = __float2half(v);
        }
    }
}

// =======================================================================
__global__ void self_attn_kernel()
{
    extern __shared__ float sh[];
    float* q = sh;
    float* k = q + 12 * 512;
    float* v = k + 12 * 512;
    float* S = v + 12 * 512;
    const int b = blockIdx.x, tid = threadIdx.x;
    for (int i = tid; i < 12 * 512; i += 128) {
        int l = i >> 9, d = i & 511;
        const float* row = g_qkv + (size_t)(l * 64 + b) * 1536;
        q[i] = row[d]; k[i] = row[512 + d]; v[i] = row[1024 + d];
    }
    __syncthreads();
    for (int i = tid; i < 144; i += 128) {
        int l = i / 12, m = i - l * 12;
        const float* qp = q + l * 512;
        const float* kp = k + m * 512;
        float s = 0.f;
        for (int e = 0; e < 512; e++) s += qp[e] * kp[e];
        S[i] = s * ATTN_SCALE;
    }
    __syncthreads();
    if (tid < 12) {
        float mx = -1e30f;
        for (int m = 0; m < 12; m++) mx = fmaxf(mx, S[tid * 12 + m]);
        float e[12], sum = 0.f;
        for (int m = 0; m < 12; m++) { e[m] = expf(S[tid * 12 + m] - mx); sum += e[m]; }
        float inv = 1.f / sum;
        for (int m = 0; m < 12; m++) S[tid * 12 + m] = e[m] * inv;
    }
    __syncthreads();
    for (int i = tid; i < 12 * 512; i += 128) {
        int l = i >> 9, d = i & 511;
        float o = 0.f;
        #pragma unroll
        for (int m = 0; m < 12; m++) o += S[l * 12 + m] * v[m * 512 + d];
        g_ao[(size_t)(b * 12 + l) * 512 + d] = o;
    }
}

// parallel bqk: grid 2 x 256, coalesced columns
__global__ void bqk_kernel(const float* __restrict__ ciw, const float* __restrict__ cib)
{
    int d = blockIdx.x * 256 + threadIdx.x;
    const float* cWk = ciw + 512 * 512;
    float s = 0.f;
    for (int e = 0; e < 512; e++) s += cib[e] * cWk[e * 512 + d];
    g_bqk[d] = s * ATTN_SCALE;
}

// parallel bov: warp per output
__global__ void bov_kernel(const float* __restrict__ cow,
                           const float* __restrict__ cib,
                           const float* __restrict__ cob)
{
    int warp = threadIdx.x >> 5, lane = threadIdx.x & 31;
    int i = blockIdx.x * 8 + warp;
    const float* cbv = cib + 1024;
    float s = 0.f;
    for (int e = lane; e < 512; e += 32) s += cow[i * 512 + e] * cbv[e];
    #pragma unroll
    for (int o = 16; o > 0; o >>= 1) s += __shfl_xor_sync(0xffffffff, s, o);
    if (lane == 0) g_bov[i] = s + cob[i];
}

__global__ void f2h_kernel(const float* __restrict__ in, __half* __restrict__ out, size_t n)
{
    size_t i = ((size_t)blockIdx.x * blockDim.x + threadIdx.x) * 4;
    if (i >= n) return;
    float4 v = *(const float4*)(in + i);
    __half2* o = (__half2*)(out + i);
    o[0] = __floats2half2_rn(v.x, v.y);
    o[1] = __floats2half2_rn(v.z, v.w);
}

// =======================================================================
// Fused cross-attention, ONE block per class, 4 m-chunks looped inside
// (text tile loaded once). grid 1000, 256 threads, dyn smem 204288 B.
// =======================================================================
__global__ void attn_cls_kernel()
{
    extern __shared__ char smc[];
    __half* th = (__half*)smc;                                     // 96 x TH_LD
    __half* aq = (__half*)(smc + 96 * TH_LD * 2);                  // 192 x AQ_LD
    float*  Ss = (float*)(smc + 96 * TH_LD * 2 + 192 * AQ_LD * 2); // 192 x SS_LD
    const int tid  = threadIdx.x;
    const int warp = tid >> 5;
    const int c    = blockIdx.x;
    const int wr = warp >> 1, wc = warp & 1;

    // text tile -> smem (padded rows), once per class
    {
        const uint4* src = (const uint4*)(g_texth + (size_t)c * (96 * 512));
        for (int i = tid; i < 96 * 64; i += 256) {
            int row = i >> 6, v = i & 63;
            *((uint4*)(th + row * TH_LD) + v) = src[i];
        }
    }
    __syncthreads();

    for (int mch = 0; mch < 4; mch++) {
        const int b0 = mch * 16;
        const __half* qbase = g_qkh + (size_t)(b0 * 12) * 512;

        // prefetch aq chunk 0 into regs
        uint4 ra[6];
        #pragma unroll
        for (int i = 0; i < 6; i++) {
            int f = tid + i * 256, r = f >> 3, v = f & 7;
            ra[i] = ((const uint4*)(qbase + (size_t)r * 512))[v];
        }

        wmma::fragment<wmma::accumulator, 16, 16, 16, float> acc[3][3];
        #pragma unroll
        for (int i = 0; i < 3; i++)
            #pragma unroll
            for (int j = 0; j < 3; j++) wmma::fill_fragment(acc[i][j], 0.f);

        for (int kc = 0; kc < 8; kc++) {
            #pragma unroll
            for (int i = 0; i < 6; i++) {
                int f = tid + i * 256, r = f >> 3, v = f & 7;
                *((uint4*)(aq + r * AQ_LD) + v) = ra[i];
            }
            __syncthreads();
            if (kc < 7) {
                #pragma unroll
                for (int i = 0; i < 6; i++) {
                    int f = tid + i * 256, r = f >> 3, v = f & 7;
                    ra[i] = ((const uint4*)(qbase + (size_t)r * 512 + (kc + 1) * 64))[v];
                }
            }
            #pragma unroll
            for (int ks = 0; ks < 4; ks++) {
                wmma::fragment<wmma::matrix_a, 16, 16, 16, __half, wmma::row_major> af[3];
                #pragma unroll
                for (int i = 0; i < 3; i++)
                    wmma::load_matrix_sync(af[i], aq + ((wr * 3 + i) * 16) * AQ_LD + ks * 16, AQ_LD);
                #pragma unroll
                for (int j = 0; j < 3; j++) {
                    wmma::fragment<wmma::matrix_b, 16, 16, 16, __half, wmma::col_major> bf;
                    wmma::load_matrix_sync(bf, th + ((wc * 3 + j) * 16) * TH_LD + kc * 64 + ks * 16, TH_LD);
                    #pragma unroll
                    for (int i = 0; i < 3; i++) wmma::mma_sync(acc[i][j], af[i], bf, acc[i][j]);
                }
            }
            __syncthreads();
        }
        #pragma unroll
        for (int i = 0; i < 3; i++)
            #pragma unroll
            for (int j = 0; j < 3; j++)
                wmma::store_matrix_sync(Ss + ((wr * 3 + i) * 16) * SS_LD + (wc * 3 + j) * 16,
                                        acc[i][j], SS_LD, wmma::mem_row_major);
        __syncthreads();

        // softmax over m, sum over l, /96 -> wsm (reuse aq)
        __half* wsm = aq;
        if (tid < 128) {
            int bl = tid >> 3, t = tid & 7;
            float wacc[12];
            #pragma unroll
            for (int m = 0; m < 12; m++) wacc[m] = 0.f;
            for (int l = 0; l < 12; l++) {
                int base = (bl * 12 + l) * SS_LD + t;
                float vals[12], mx = -1e30f;
                #pragma unroll
                for (int m = 0; m < 12; m++) { vals[m] = Ss[base + m * 8]; mx = fmaxf(mx, vals[m]); }
                float sum = 0.f;
                #pragma unroll
                for (int m = 0; m < 12; m++) { vals[m] = __expf(vals[m] - mx); sum += vals[m]; }
                float inv = 1.f / sum;
                #pragma unroll
                for (int m = 0; m < 12; m++) wacc[m] += vals[m] * inv;
            }
            #pragma unroll
            for (int m = 0; m < 12; m++)
                wsm[bl * 96 + m * 8 + t] = __float2half(wacc[m] * (1.f / 96.f));
        }
        __syncthreads();

        // rc = w @ text -> stage [16 x TH_LD] f32 in Ss
        {
            wmma::fragment<wmma::accumulator, 16, 16, 16, float> rca[4];
            #pragma unroll
            for (int j = 0; j < 4; j++) wmma::fill_fragment(rca[j], 0.f);
            #pragma unroll
            for (int kt = 0; kt < 6; kt++) {
                wmma::fragment<wmma::matrix_a, 16, 16, 16, __half, wmma::row_major> af;
                wmma::load_matrix_sync(af, wsm + kt * 16, 96);
                #pragma unroll
                for (int j = 0; j < 4; j++) {
                    wmma::fragment<wmma::matrix_b, 16, 16, 16, __half, wmma::row_major> bf;
                    wmma::load_matrix_sync(bf, th + (kt * 16) * TH_LD + (warp * 4 + j) * 16, TH_LD);
                    wmma::mma_sync(rca[j], af, bf, rca[j]);
                }
            }
            #pragma unroll
            for (int j = 0; j < 4; j++)
                wmma::store_matrix_sync(Ss + (warp * 4 + j) * 16, rca[j], TH_LD, wmma::mem_row_major);
        }
        __syncthreads();

        for (int i = tid; i < 16 * 512; i += 256) {
            int bl = i >> 9, d = i & 511;
            g_rch[((size_t)(b0 + bl) * 1000 + c) * 512 + d] = __float2half(Ss[bl * TH_LD + d]);
        }
        __syncthreads();
    }
}

// =======================================================================
// txt = rc @ Wov^T  (bias deferred). M=64000,N=512,K=512. grid (4,500).
// =======================================================================
__global__ void txt_gemm_kernel()
{
    __shared__ __half As[128 * 72];
    __shared__ __half Bs[128 * 72];
    const int tid = threadIdx.x, warp = tid >> 5;
    const size_t m0 = (size_t)blockIdx.y * 128;
    const int n0 = blockIdx.x * 128;
    const int wr = warp >> 1, wc = warp & 1;
    uint4 ra[4], rb[4];
    wmma::fragment<wmma::accumulator, 16, 16, 16, float> acc[2][4];
    #pragma unroll
    for (int i = 0; i < 2; i++)
        #pragma unroll
        for (int j = 0; j < 4; j++) wmma::fill_fragment(acc[i][j], 0.f);

    #pragma unroll
    for (int i = 0; i < 4; i++) {
        int f = tid + i * 256, r = f >> 3, v = f & 7;
        ra[i] = ((const uint4*)(g_rch + (m0 + r) * 512))[v];
        rb[i] = ((const uint4*)(g_Wovh + (size_t)(n0 + r) * 512))[v];
    }
    for (int kc = 0; kc < 8; kc++) {
        #pragma unroll
        for (int i = 0; i < 4; i++) {
            int f = tid + i * 256, r = f >> 3, v = f & 7;
            *((uint4*)(As + r * 72) + v) = ra[i];
            *((uint4*)(Bs + r * 72) + v) = rb[i];
        }
        __syncthreads();
        if (kc < 7) {
            int kk = (kc + 1) * 64;
            #pragma unroll
            for (int i = 0; i < 4; i++) {
                int f = tid + i * 256, r = f >> 3, v = f & 7;
                ra[i] = ((const uint4*)(g_rch + (m0 + r) * 512 + kk))[v];
                rb[i] = ((const uint4*)(g_Wovh + (size_t)(n0 + r) * 512 + kk))[v];
            }
        }
        #pragma unroll
        for (int ks = 0; ks < 4; ks++) {
            wmma::fragment<wmma::matrix_a, 16, 16, 16, __half, wmma::row_major> af[2];
            #pragma unroll
            for (int i = 0; i < 2; i++)
                wmma::load_matrix_sync(af[i], As + ((wr * 2 + i) * 16) * 72 + ks * 16, 72);
            #pragma unroll
            for (int j = 0; j < 4; j++) {
                wmma::fragment<wmma::matrix_b, 16, 16, 16, __half, wmma::col_major> bf;
                wmma::load_matrix_sync(bf, Bs + ((wc * 4 + j) * 16) * 72 + ks * 16, 72);
                #pragma unroll
                for (int i = 0; i < 2; i++) wmma::mma_sync(acc[i][j], af[i], bf, acc[i][j]);
            }
        }
        __syncthreads();
    }
    #pragma unroll
    for (int i = 0; i < 2; i++)
        #pragma unroll
        for (int j = 0; j < 4; j++)
            wmma::store_matrix_sync(g_txt + (m0 + (wr * 2 + i) * 16) * 512 + n0 + (wc * 4 + j) * 16,
                                    acc[i][j], 512, wmma::mem_row_major);
}

__global__ void colnorm_partial()
{
    const int b = blockIdx.y, chunk = blockIdx.x, d = threadIdx.x;
    const float bv = g_bov[d];
    float acc = 0.f;
    const int cs = chunk * 125;
    for (int c = cs; c < cs + 125; c++) {
        float v = g_txt[((size_t)b * 1000 + c) * 512 + d] + bv;
        acc += v * v;
    }
    g_part[(size_t)(chunk * 64 + b) * 512 + d] = acc;
}

__global__ void make_h_kernel()
{
    __shared__ float red[512];
    const int b = blockIdx.x, d = threadIdx.x;
    float nrm2 = 0.f;
    #pragma unroll
    for (int p = 0; p < 8; p++) nrm2 += g_part[(size_t)(p * 64 + b) * 512 + d];
    float iv = g_xs[(size_t)(b * 12 + 11) * 512 + d];
    red[d] = iv * iv;
    __syncthreads();
    for (int s = 256; s > 0; s >>= 1) {
        if (d < s) red[d] += red[d + s];
        __syncthreads();
    }
    g_h[b * 512 + d] = iv * rsqrtf(red[0]) * rsqrtf(nrm2);
}

__global__ void logits_kernel(const float* __restrict__ ls, float* __restrict__ out)
{
    __shared__ float hs[512], bs[512];
    const int b = blockIdx.y;
    const int tid = threadIdx.x, warp = tid >> 5, lane = tid & 31;
    const int c = blockIdx.x * 8 + warp;
    for (int i = tid; i < 512; i += 256) { hs[i] = g_h[b * 512 + i]; bs[i] = g_bov[i]; }
    __syncthreads();
    const float* row = g_txt + ((size_t)b * 1000 + c) * 512;
    float acc = 0.f;
    for (int kk = lane; kk < 512; kk += 32) acc += hs[kk] * (row[kk] + bs[kk]);
    #pragma unroll
    for (int off = 16; off > 0; off >>= 1) acc += __shfl_xor_sync(0xffffffff, acc, off);
    if (lane == 0) out[(size_t)b * 1000 + c] = expf(ls[0]) * acc;
}

// =======================================================================
extern "C" void kernel_launch(void* const* d_in, const int* in_sizes, int n_in,
                              void* d_out, int out_size)
{
    const float* x   = (const float*)d_in[0];
    const float* txt = (const float*)d_in[1];
    const float* siw = (const float*)d_in[2];
    const float* sib = (const float*)d_in[3];
    const float* sow = (const float*)d_in[4];
    const float* sob = (const float*)d_in[5];
    const float* ciw = (const float*)d_in[6];
    const float* cib = (const float*)d_in[7];
    const float* cow = (const float*)d_in[8];
    const float* cob = (const float*)d_in[9];
    const float* ls  = (const float*)d_in[10];
    float* out = (float*)d_out;

    float *p_qkv, *p_ao, *p_xs, *p_W2, *p_bqk;
    __half *p_qkh, *p_texth, *p_Wovh;
    cudaGetSymbolAddress((void**)&p_qkv,   g_qkv);
    cudaGetSymbolAddress((void**)&p_ao,    g_ao);
    cudaGetSymbolAddress((void**)&p_xs,    g_xs);
    cudaGetSymbolAddress((void**)&p_W2,    g_W2);
    cudaGetSymbolAddress((void**)&p_bqk,   g_bqk);
    cudaGetSymbolAddress((void**)&p_qkh,   g_qkh);
    cudaGetSymbolAddress((void**)&p_texth, g_texth);
    cudaGetSymbolAddress((void**)&p_Wovh,  g_Wovh);

    cudaFuncSetAttribute(self_attn_kernel, cudaFuncAttributeMaxDynamicSharedMemorySize, 74304);
    cudaFuncSetAttribute(attn_cls_kernel,  cudaFuncAttributeMaxDynamicSharedMemorySize, 204288);

    // ---- prologue ----
    gemm_f32<<<dim3(24, 12), 256>>>(x, 512, 1, siw, 1, 512, sib, 1.f, p_qkv, nullptr, 1536, 512);
    gemm_f32<<<dim3(8, 8), 256>>>(ciw, 1, 512, ciw + 512 * 512, 512, 1, nullptr, ATTN_SCALE,
                                  p_W2, nullptr, 512, 512);
    gemm_f32<<<dim3(8, 8), 256>>>(cow, 512, 1, ciw + 1024 * 512, 512, 1, nullptr, 1.f,
                                  nullptr, p_Wovh, 512, 512);
    bqk_kernel<<<2, 256>>>(ciw, cib);
    bov_kernel<<<64, 256>>>(cow, cib, cob);

    self_attn_kernel<<<64, 128, 74304>>>();
    gemm_f32<<<dim3(8, 12), 256>>>(p_ao, 512, 1, sow, 1, 512, sob, 1.f, p_xs, nullptr, 512, 512);
    // qk = xs @ W2 + bqk (pre-scaled) -> half
    gemm_f32<<<dim3(8, 12), 256>>>(p_xs, 512, 1, p_W2, 512, 1, p_bqk, 1.f,
                                   nullptr, p_qkh, 512, 512);

    f2h_kernel<<<48000, 256>>>(txt, p_texth, (size_t)1000 * 96 * 512);

    // fused cross-attention (text loaded once per class)
    attn_cls_kernel<<<1000, 256, 204288>>>();

    // projection + norms + logits
    txt_gemm_kernel<<<dim3(4, 500), 256>>>();
    colnorm_partial<<<dim3(8, 64), 512>>>();
    make_h_kernel<<<64, 512>>>();
    logits_kernel<<<dim3(125, 64), 256>>>(ls, out);
}

// round 7
// speedup vs baseline: 5.3132x; 1.2242x over previous
#include <cuda_runtime.h>
#include <cuda_fp16.h>
#include <cstdint>
#include <mma.h>

using namespace nvcuda;

#define ATTN_SCALE 0.044194173824159216f  // 1/sqrt(512)
#define TH_LD 520   // text tile leading dim (halves)
#define SS_LD 100   // S staging leading dim (floats)

// ---------------- static device scratch ----------------
__device__ __align__(16) __half g_xh   [768 * 512];
__device__ __align__(16) __half g_siwh [1536 * 512];
__device__ __align__(16) __half g_sowh [512 * 512];
__device__ __align__(16) __half g_cWkh [512 * 512];
__device__ __align__(16) __half g_cWvh [512 * 512];
__device__ __align__(16) __half g_cWqTh[512 * 512];
__device__ __align__(16) __half g_cowh [512 * 512];
__device__ __align__(16) float  g_qkv  [768 * 1536];
__device__ __align__(16) __half g_aoh  [768 * 512];
__device__ __align__(16) float  g_xs   [768 * 512];
__device__ __align__(16) __half g_xsh  [768 * 512];
__device__ __align__(16) __half g_W2h  [512 * 512];
__device__ __align__(16) float  g_bqk  [512];
__device__ __align__(16) __half g_qkh  [768 * 512];
__device__ __align__(16) __half g_Wovh [512 * 512];
__device__ __align__(16) float  g_bov  [512];
__device__ __align__(16) __half g_rch  [(size_t)64 * 1000 * 512];
__device__ __align__(16) float  g_txt  [(size_t)64 * 1000 * 512];
__device__ __align__(16) float  g_part [8 * 64 * 512];
__device__ __align__(16) float  g_h    [64 * 512];

// ---------------- cp.async helpers ----------------
__device__ __forceinline__ void cpasync16(uint32_t dst, const void* src) {
    asm volatile("cp.async.cg.shared.global [%0], [%1], 16;"
                 :: "r"(dst), "l"(__cvta_generic_to_global(src)));
}
__device__ __forceinline__ uint32_t smem_u32(const void* p) {
    uint32_t a;
    asm("{ .reg .u64 t; cvta.to.shared.u64 t, %1; cvt.u32.u64 %0, t; }" : "=r"(a) : "l"(p));
    return a;
}
#define CP_COMMIT() asm volatile("cp.async.commit_group;" ::: "memory")
#define CP_WAIT0()  asm volatile("cp.async.wait_group 0;" ::: "memory")

// =======================================================================
// fp32 -> fp16 bulk convert
// =======================================================================
__global__ void f2h_kernel(const float* __restrict__ in, __half* __restrict__ out, size_t n)
{
    size_t i = ((size_t)blockIdx.x * blockDim.x + threadIdx.x) * 4;
    if (i >= n) return;
    float4 v = *(const float4*)(in + i);
    __half2* o = (__half2*)(out + i);
    o[0] = __floats2half2_rn(v.x, v.y);
    o[1] = __floats2half2_rn(v.z, v.w);
}

// 512x512 transpose + convert: out[m,k] = in[k,m]
__global__ void f2h_t(const float* __restrict__ in, __half* __restrict__ out)
{
    __shared__ float t[32][33];
    const int tx = threadIdx.x & 31, ty = threadIdx.x >> 5;
    const int bx = blockIdx.x * 32, by = blockIdx.y * 32;
    #pragma unroll
    for (int j = 0; j < 4; j++)
        t[ty + j * 8][tx] = in[(size_t)(by + ty + j * 8) * 512 + bx + tx];
    __syncthreads();
    #pragma unroll
    for (int j = 0; j < 4; j++)
        out[(size_t)(bx + ty + j * 8) * 512 + by + tx] = __float2half(t[tx][ty + j * 8]);
}

// =======================================================================
// Generic half GEMM (prologue): C[m,n] = scale*sum_k A[m,k]*B(k,n) + bias[n]
// A: half row-major [M,K]. bt==1: B is [N,K] (NT); bt==0: B is [K,N] (NN).
// Tile 64x64, k-chunk 64, 256 threads (8 warps).
// =======================================================================
__global__ void hgemm(const __half* __restrict__ A, const __half* __restrict__ B, int bt,
                      const float* __restrict__ bias, float scale,
                      float* __restrict__ Cf, __half* __restrict__ Ch,
                      int N, int K)
{
    __shared__ __half As[64 * 72];
    __shared__ __half Bs[64 * 72];
    __shared__ float  Cs[64 * 68];
    const int tid = threadIdx.x, warp = tid >> 5;
    const int m0 = blockIdx.y * 64, n0 = blockIdx.x * 64;
    const int wr = warp >> 1, wc = warp & 1;

    wmma::fragment<wmma::accumulator, 16, 16, 16, float> acc[2];
    wmma::fill_fragment(acc[0], 0.f);
    wmma::fill_fragment(acc[1], 0.f);

    uint4 ra[2], rb[2];
    #pragma unroll
    for (int i = 0; i < 2; i++) {
        int f = tid + i * 256, r = f >> 3, v = f & 7;
        ra[i] = ((const uint4*)(A + (size_t)(m0 + r) * K))[v];
        rb[i] = bt ? ((const uint4*)(B + (size_t)(n0 + r) * K))[v]
                   : ((const uint4*)(B + (size_t)r * N + n0))[v];
    }
    const int nk = K >> 6;
    for (int kc = 0; kc < nk; kc++) {
        #pragma unroll
        for (int i = 0; i < 2; i++) {
            int f = tid + i * 256, r = f >> 3, v = f & 7;
            *((uint4*)(As + r * 72) + v) = ra[i];
            *((uint4*)(Bs + r * 72) + v) = rb[i];
        }
        __syncthreads();
        if (kc + 1 < nk) {
            int kk = (kc + 1) << 6;
            #pragma unroll
            for (int i = 0; i < 2; i++) {
                int f = tid + i * 256, r = f >> 3, v = f & 7;
                ra[i] = ((const uint4*)(A + (size_t)(m0 + r) * K + kk))[v];
                rb[i] = bt ? ((const uint4*)(B + (size_t)(n0 + r) * K + kk))[v]
                           : ((const uint4*)(B + (size_t)(kk + r) * N + n0))[v];
            }
        }
        #pragma unroll
        for (int ks = 0; ks < 4; ks++) {
            wmma::fragment<wmma::matrix_a, 16, 16, 16, __half, wmma::row_major> af;
            wmma::load_matrix_sync(af, As + (wr * 16) * 72 + ks * 16, 72);
            if (bt) {
                #pragma unroll
                for (int j = 0; j < 2; j++) {
                    wmma::fragment<wmma::matrix_b, 16, 16, 16, __half, wmma::col_major> bf;
                    wmma::load_matrix_sync(bf, Bs + ((wc * 2 + j) * 16) * 72 + ks * 16, 72);
                    wmma::mma_sync(acc[j], af, bf, acc[j]);
                }
            } else {
                #pragma unroll
                for (int j = 0; j < 2; j++) {
                    wmma::fragment<wmma::matrix_b, 16, 16, 16, __half, wmma::row_major> bf;
                    wmma::load_matrix_sync(bf, Bs + (ks * 16) * 72 + (wc * 2 + j) * 16, 72);
                    wmma::mma_sync(acc[j], af, bf, acc[j]);
                }
            }
        }
        __syncthreads();
    }
    wmma::store_matrix_sync(Cs + (wr * 16) * 68 + wc * 32,      acc[0], 68, wmma::mem_row_major);
    wmma::store_matrix_sync(Cs + (wr * 16) * 68 + wc * 32 + 16, acc[1], 68, wmma::mem_row_major);
    __syncthreads();
    for (int i = tid; i < 4096; i += 256) {
        int r = i >> 6, n = i & 63;
        float v = Cs[r * 68 + n] * scale + (bias ? bias[n0 + n] : 0.f);
        size_t m = m0 + r;
        if (Cf) Cf[m * N + n0 + n] = v;
        if (Ch) Ch[m * N + n0 + n] = __float2half(v);
    }
}

// =======================================================================
// self-attention over the 12-layer axis; reads g_qkv f32, writes g_aoh half
// =======================================================================
__global__ void self_attn_kernel()
{
    extern __shared__ float sh[];
    float* q = sh;
    float* k = q + 12 * 512;
    float* v = k + 12 * 512;
    float* S = v + 12 * 512;
    const int b = blockIdx.x, tid = threadIdx.x;
    for (int i = tid; i < 12 * 512; i += 128) {
        int l = i >> 9, d = i & 511;
        const float* row = g_qkv + (size_t)(l * 64 + b) * 1536;
        q[i] = row[d]; k[i] = row[512 + d]; v[i] = row[1024 + d];
    }
    __syncthreads();
    for (int i = tid; i < 144; i += 128) {
        int l = i / 12, m = i - l * 12;
        const float* qp = q + l * 512;
        const float* kp = k + m * 512;
        float s = 0.f;
        for (int e = 0; e < 512; e++) s += qp[e] * kp[e];
        S[i] = s * ATTN_SCALE;
    }
    __syncthreads();
    if (tid < 12) {
        float mx = -1e30f;
        for (int m = 0; m < 12; m++) mx = fmaxf(mx, S[tid * 12 + m]);
        float e[12], sum = 0.f;
        for (int m = 0; m < 12; m++) { e[m] = expf(S[tid * 12 + m] - mx); sum += e[m]; }
        float inv = 1.f / sum;
        for (int m = 0; m < 12; m++) S[tid * 12 + m] = e[m] * inv;
    }
    __syncthreads();
    for (int i = tid; i < 12 * 512; i += 128) {
        int l = i >> 9, d = i & 511;
        float o = 0.f;
        #pragma unroll
        for (int m = 0; m < 12; m++) o += S[l * 12 + m] * v[m * 512 + d];
        g_aoh[(size_t)(b * 12 + l) * 512 + d] = __float2half(o);
    }
}

// bqk: grid 16 x 256; 8 e-chunks per 32 d-outputs, smem reduce
__global__ void bqk_kernel(const float* __restrict__ ciw, const float* __restrict__ cib)
{
    __shared__ float red[8][33];
    const int dd = threadIdx.x & 31, eg = threadIdx.x >> 5;
    const int d = blockIdx.x * 32 + dd;
    const float* cWk = ciw + 512 * 512;
    float s = 0.f;
    const int e0 = eg * 64;
    #pragma unroll 8
    for (int e = e0; e < e0 + 64; e++) s += cib[e] * cWk[(size_t)e * 512 + d];
    red[eg][dd] = s;
    __syncthreads();
    if (eg == 0) {
        float t = 0.f;
        #pragma unroll
        for (int i = 0; i < 8; i++) t += red[i][dd];
        g_bqk[d] = t * ATTN_SCALE;
    }
}

// bov: warp per output
__global__ void bov_kernel(const float* __restrict__ cow,
                           const float* __restrict__ cib,
                           const float* __restrict__ cob)
{
    int warp = threadIdx.x >> 5, lane = threadIdx.x & 31;
    int i = blockIdx.x * 8 + warp;
    const float* cbv = cib + 1024;
    float s = 0.f;
    for (int e = lane; e < 512; e += 32) s += cow[i * 512 + e] * cbv[e];
    #pragma unroll
    for (int o = 16; o > 0; o >>= 1) s += __shfl_xor_sync(0xffffffff, s, o);
    if (lane == 0) g_bov[i] = s + cob[i];
}

// =======================================================================
// Fused cross-attention, one block per class, 4 m-chunks inside.
// Text read fp32 from input (converted in smem store). cp.async aq pipeline.
// smem: th[0,99840) | aq bufs [99840, 99840+2*27648) | Ss overlaps at 99840
//       (192*100*4 = 76800 -> ends 176640) | wsm [176640, 188928)
// =======================================================================
#define AQ0 99840
#define AQB 27648
#define WSM 176640

__global__ void attn_cls_kernel(const float* __restrict__ textf)
{
    extern __shared__ char smc[];
    __half* th  = (__half*)smc;
    float*  Ss  = (float*)(smc + AQ0);
    __half* wsm = (__half*)(smc + WSM);
    const uint32_t aqs = smem_u32(smc) + AQ0;
    const int tid  = threadIdx.x;
    const int warp = tid >> 5;
    const int c    = blockIdx.x;
    const int wr = warp >> 1, wc = warp & 1;

    // text tile fp32 -> half smem (padded rows), once per class
    {
        const float4* src = (const float4*)(textf + (size_t)c * (96 * 512));
        for (int i = tid; i < 96 * 128; i += 256) {
            int row = i >> 7, v = i & 127;
            float4 f = src[row * 128 + v];
            __half2* dst = (__half2*)(th + row * TH_LD + v * 4);
            dst[0] = __floats2half2_rn(f.x, f.y);
            dst[1] = __floats2half2_rn(f.z, f.w);
        }
    }
    __syncthreads();

    for (int mch = 0; mch < 4; mch++) {
        const int b0 = mch * 16;
        const __half* qbase = g_qkh + (size_t)(b0 * 12) * 512;

        // issue aq chunk 0
        #pragma unroll
        for (int i = 0; i < 6; i++) {
            int f = tid + i * 256, r = f >> 3, v = f & 7;
            cpasync16(aqs + r * 144 + v * 16, qbase + (size_t)r * 512 + v * 8);
        }
        CP_COMMIT();

        wmma::fragment<wmma::accumulator, 16, 16, 16, float> acc[3][3];
        #pragma unroll
        for (int i = 0; i < 3; i++)
            #pragma unroll
            for (int j = 0; j < 3; j++) wmma::fill_fragment(acc[i][j], 0.f);

        for (int kc = 0; kc < 8; kc++) {
            CP_WAIT0();
            __syncthreads();
            if (kc < 7) {
                uint32_t nbuf = aqs + ((kc + 1) & 1) * AQB;
                #pragma unroll
                for (int i = 0; i < 6; i++) {
                    int f = tid + i * 256, r = f >> 3, v = f & 7;
                    cpasync16(nbuf + r * 144 + v * 16,
                              qbase + (size_t)r * 512 + (kc + 1) * 64 + v * 8);
                }
                CP_COMMIT();
            }
            const __half* aq = (const __half*)(smc + AQ0 + (kc & 1) * AQB);
            #pragma unroll
            for (int ks = 0; ks < 4; ks++) {
                wmma::fragment<wmma::matrix_a, 16, 16, 16, __half, wmma::row_major> af[3];
                #pragma unroll
                for (int i = 0; i < 3; i++)
                    wmma::load_matrix_sync(af[i], aq + ((wr * 3 + i) * 16) * 72 + ks * 16, 72);
                #pragma unroll
                for (int j = 0; j < 3; j++) {
                    wmma::fragment<wmma::matrix_b, 16, 16, 16, __half, wmma::col_major> bf;
                    wmma::load_matrix_sync(bf, th + ((wc * 3 + j) * 16) * TH_LD + kc * 64 + ks * 16, TH_LD);
                    #pragma unroll
                    for (int i = 0; i < 3; i++) wmma::mma_sync(acc[i][j], af[i], bf, acc[i][j]);
                }
            }
        }
        __syncthreads();   // all warps done with aq before Ss overwrites it
        #pragma unroll
        for (int i = 0; i < 3; i++)
            #pragma unroll
            for (int j = 0; j < 3; j++)
                wmma::store_matrix_sync(Ss + ((wr * 3 + i) * 16) * SS_LD + (wc * 3 + j) * 16,
                                        acc[i][j], SS_LD, wmma::mem_row_major);
        __syncthreads();

        // softmax over m, sum over l, /96 -> wsm
        if (tid < 128) {
            int bl = tid >> 3, t = tid & 7;
            float wacc[12];
            #pragma unroll
            for (int m = 0; m < 12; m++) wacc[m] = 0.f;
            for (int l = 0; l < 12; l++) {
                int base = (bl * 12 + l) * SS_LD + t;
                float vals[12], mx = -1e30f;
                #pragma unroll
                for (int m = 0; m < 12; m++) { vals[m] = Ss[base + m * 8]; mx = fmaxf(mx, vals[m]); }
                float sum = 0.f;
                #pragma unroll
                for (int m = 0; m < 12; m++) { vals[m] = __expf(vals[m] - mx); sum += vals[m]; }
                float inv = 1.f / sum;
                #pragma unroll
                for (int m = 0; m < 12; m++) wacc[m] += vals[m] * inv;
            }
            #pragma unroll
            for (int m = 0; m < 12; m++)
                wsm[bl * 96 + m * 8 + t] = __float2half(wacc[m] * (1.f / 96.f));
        }
        __syncthreads();

        // rc = w @ text -> stage [16 x TH_LD] f32 in Ss
        {
            wmma::fragment<wmma::accumulator, 16, 16, 16, float> rca[4];
            #pragma unroll
            for (int j = 0; j < 4; j++) wmma::fill_fragment(rca[j], 0.f);
            #pragma unroll
            for (int kt = 0; kt < 6; kt++) {
                wmma::fragment<wmma::matrix_a, 16, 16, 16, __half, wmma::row_major> af;
                wmma::load_matrix_sync(af, wsm + kt * 16, 96);
                #pragma unroll
                for (int j = 0; j < 4; j++) {
                    wmma::fragment<wmma::matrix_b, 16, 16, 16, __half, wmma::row_major> bf;
                    wmma::load_matrix_sync(bf, th + (kt * 16) * TH_LD + (warp * 4 + j) * 16, TH_LD);
                    wmma::mma_sync(rca[j], af, bf, rca[j]);
                }
            }
            #pragma unroll
            for (int j = 0; j < 4; j++)
                wmma::store_matrix_sync(Ss + (warp * 4 + j) * 16, rca[j], TH_LD, wmma::mem_row_major);
        }
        __syncthreads();

        for (int i = tid; i < 16 * 512; i += 256) {
            int bl = i >> 9, d = i & 511;
            g_rch[((size_t)(b0 + bl) * 1000 + c) * 512 + d] = __float2half(Ss[bl * TH_LD + d]);
        }
        __syncthreads();
    }
}

// =======================================================================
// txt = rc @ Wov^T  (bias deferred). M=64000,N=512,K=512. grid (4,500).
// =======================================================================
__global__ void txt_gemm_kernel()
{
    __shared__ __half As[128 * 72];
    __shared__ __half Bs[128 * 72];
    const int tid = threadIdx.x, warp = tid >> 5;
    const size_t m0 = (size_t)blockIdx.y * 128;
    const int n0 = blockIdx.x * 128;
    const int wr = warp >> 1, wc = warp & 1;
    uint4 ra[4], rb[4];
    wmma::fragment<wmma::accumulator, 16, 16, 16, float> acc[2][4];
    #pragma unroll
    for (int i = 0; i < 2; i++)
        #pragma unroll
        for (int j = 0; j < 4; j++) wmma::fill_fragment(acc[i][j], 0.f);

    #pragma unroll
    for (int i = 0; i < 4; i++) {
        int f = tid + i * 256, r = f >> 3, v = f & 7;
        ra[i] = ((const uint4*)(g_rch + (m0 + r) * 512))[v];
        rb[i] = ((const uint4*)(g_Wovh + (size_t)(n0 + r) * 512))[v];
    }
    for (int kc = 0; kc < 8; kc++) {
        #pragma unroll
        for (int i = 0; i < 4; i++) {
            int f = tid + i * 256, r = f >> 3, v = f & 7;
            *((uint4*)(As + r * 72) + v) = ra[i];
            *((uint4*)(Bs + r * 72) + v) = rb[i];
        }
        __syncthreads();
        if (kc < 7) {
            int kk = (kc + 1) * 64;
            #pragma unroll
            for (int i = 0; i < 4; i++) {
                int f = tid + i * 256, r = f >> 3, v = f & 7;
                ra[i] = ((const uint4*)(g_rch + (m0 + r) * 512 + kk))[v];
                rb[i] = ((const uint4*)(g_Wovh + (size_t)(n0 + r) * 512 + kk))[v];
            }
        }
        #pragma unroll
        for (int ks = 0; ks < 4; ks++) {
            wmma::fragment<wmma::matrix_a, 16, 16, 16, __half, wmma::row_major> af[2];
            #pragma unroll
            for (int i = 0; i < 2; i++)
                wmma::load_matrix_sync(af[i], As + ((wr * 2 + i) * 16) * 72 + ks * 16, 72);
            #pragma unroll
            for (int j = 0; j < 4; j++) {
                wmma::fragment<wmma::matrix_b, 16, 16, 16, __half, wmma::col_major> bf;
                wmma::load_matrix_sync(bf, Bs + ((wc * 4 + j) * 16) * 72 + ks * 16, 72);
                #pragma unroll
                for (int i = 0; i < 2; i++) wmma::mma_sync(acc[i][j], af[i], bf, acc[i][j]);
            }
        }
        __syncthreads();
    }
    #pragma unroll
    for (int i = 0; i < 2; i++)
        #pragma unroll
        for (int j = 0; j < 4; j++)
            wmma::store_matrix_sync(g_txt + (m0 + (wr * 2 + i) * 16) * 512 + n0 + (wc * 4 + j) * 16,
                                    acc[i][j], 512, wmma::mem_row_major);
}

__global__ void colnorm_partial()
{
    const int b = blockIdx.y, chunk = blockIdx.x, d = threadIdx.x;
    const float bv = g_bov[d];
    float acc = 0.f;
    const int cs = chunk * 125;
    for (int c = cs; c < cs + 125; c++) {
        float v = g_txt[((size_t)b * 1000 + c) * 512 + d] + bv;
        acc += v * v;
    }
    g_part[(size_t)(chunk * 64 + b) * 512 + d] = acc;
}

__global__ void make_h_kernel()
{
    __shared__ float red[512];
    const int b = blockIdx.x, d = threadIdx.x;
    float nrm2 = 0.f;
    #pragma unroll
    for (int p = 0; p < 8; p++) nrm2 += g_part[(size_t)(p * 64 + b) * 512 + d];
    float iv = g_xs[(size_t)(b * 12 + 11) * 512 + d];
    red[d] = iv * iv;
    __syncthreads();
    for (int s = 256; s > 0; s >>= 1) {
        if (d < s) red[d] += red[d + s];
        __syncthreads();
    }
    g_h[b * 512 + d] = iv * rsqrtf(red[0]) * rsqrtf(nrm2);
}

__global__ void logits_kernel(const float* __restrict__ ls, float* __restrict__ out)
{
    __shared__ float hs[512], bs[512];
    const int b = blockIdx.y;
    const int tid = threadIdx.x, warp = tid >> 5, lane = tid & 31;
    const int c = blockIdx.x * 8 + warp;
    for (int i = tid; i < 512; i += 256) { hs[i] = g_h[b * 512 + i]; bs[i] = g_bov[i]; }
    __syncthreads();
    const float* row = g_txt + ((size_t)b * 1000 + c) * 512;
    float acc = 0.f;
    for (int kk = lane; kk < 512; kk += 32) acc += hs[kk] * (row[kk] + bs[kk]);
    #pragma unroll
    for (int off = 16; off > 0; off >>= 1) acc += __shfl_xor_sync(0xffffffff, acc, off);
    if (lane == 0) out[(size_t)b * 1000 + c] = expf(ls[0]) * acc;
}

// =======================================================================
extern "C" void kernel_launch(void* const* d_in, const int* in_sizes, int n_in,
                              void* d_out, int out_size)
{
    const float* x   = (const float*)d_in[0];
    const float* txt = (const float*)d_in[1];
    const float* siw = (const float*)d_in[2];
    const float* sib = (const float*)d_in[3];
    const float* sow = (const float*)d_in[4];
    const float* sob = (const float*)d_in[5];
    const float* ciw = (const float*)d_in[6];
    const float* cib = (const float*)d_in[7];
    const float* cow = (const float*)d_in[8];
    const float* cob = (const float*)d_in[9];
    const float* ls  = (const float*)d_in[10];
    float* out = (float*)d_out;

    __half *p_xh, *p_siwh, *p_sowh, *p_cWkh, *p_cWvh, *p_cWqTh, *p_cowh;
    __half *p_aoh, *p_xsh, *p_W2h, *p_qkh, *p_Wovh;
    float  *p_qkv, *p_xs, *p_bqk;
    cudaGetSymbolAddress((void**)&p_xh,    g_xh);
    cudaGetSymbolAddress((void**)&p_siwh,  g_siwh);
    cudaGetSymbolAddress((void**)&p_sowh,  g_sowh);
    cudaGetSymbolAddress((void**)&p_cWkh,  g_cWkh);
    cudaGetSymbolAddress((void**)&p_cWvh,  g_cWvh);
    cudaGetSymbolAddress((void**)&p_cWqTh, g_cWqTh);
    cudaGetSymbolAddress((void**)&p_cowh,  g_cowh);
    cudaGetSymbolAddress((void**)&p_qkv,   g_qkv);
    cudaGetSymbolAddress((void**)&p_aoh,   g_aoh);
    cudaGetSymbolAddress((void**)&p_xs,    g_xs);
    cudaGetSymbolAddress((void**)&p_xsh,   g_xsh);
    cudaGetSymbolAddress((void**)&p_W2h,   g_W2h);
    cudaGetSymbolAddress((void**)&p_bqk,   g_bqk);
    cudaGetSymbolAddress((void**)&p_qkh,   g_qkh);
    cudaGetSymbolAddress((void**)&p_Wovh,  g_Wovh);

    cudaFuncSetAttribute(self_attn_kernel, cudaFuncAttributeMaxDynamicSharedMemorySize, 74304);
    cudaFuncSetAttribute(attn_cls_kernel,  cudaFuncAttributeMaxDynamicSharedMemorySize, 188928);

    // ---- conversions ----
    f2h_kernel<<<384, 256>>>(x,   p_xh,   (size_t)768 * 512);
    f2h_kernel<<<768, 256>>>(siw, p_siwh, (size_t)1536 * 512);
    f2h_kernel<<<256, 256>>>(sow, p_sowh, (size_t)512 * 512);
    f2h_kernel<<<256, 256>>>(ciw + 512 * 512,  p_cWkh, (size_t)512 * 512);
    f2h_kernel<<<256, 256>>>(ciw + 1024 * 512, p_cWvh, (size_t)512 * 512);
    f2h_kernel<<<256, 256>>>(cow, p_cowh, (size_t)512 * 512);
    f2h_t<<<dim3(16, 16), 256>>>(ciw, p_cWqTh);

    // ---- prologue GEMMs (wmma) ----
    // qkv = x @ siw^T + sib
    hgemm<<<dim3(24, 12), 256>>>(p_xh, p_siwh, 1, sib, 1.f, p_qkv, nullptr, 1536, 512);
    // W2 = scale * cWq^T @ cWk
    hgemm<<<dim3(8, 8), 256>>>(p_cWqTh, p_cWkh, 0, nullptr, ATTN_SCALE, nullptr, p_W2h, 512, 512);
    // Wov = cow @ cWv
    hgemm<<<dim3(8, 8), 256>>>(p_cowh, p_cWvh, 0, nullptr, 1.f, nullptr, p_Wovh, 512, 512);
    bqk_kernel<<<16, 256>>>(ciw, cib);
    bov_kernel<<<64, 256>>>(cow, cib, cob);

    self_attn_kernel<<<64, 128, 74304>>>();
    // xs = ao @ sow^T + sob  (f32 + half outputs)
    hgemm<<<dim3(8, 12), 256>>>(p_aoh, p_sowh, 1, sob, 1.f, p_xs, p_xsh, 512, 512);
    // qk = xs @ W2 + bqk (pre-scaled)
    hgemm<<<dim3(8, 12), 256>>>(p_xsh, p_W2h, 0, p_bqk, 1.f, nullptr, p_qkh, 512, 512);

    // fused cross-attention (text fp32 read once per class)
    attn_cls_kernel<<<1000, 256, 188928>>>(txt);

    // projection + norms + logits
    txt_gemm_kernel<<<dim3(4, 500), 256>>>();
    colnorm_partial<<<dim3(8, 64), 512>>>();
    make_h_kernel<<<64, 512>>>();
    logits_kernel<<<dim3(125, 64), 256>>>(ls, out);
}

// round 8
// speedup vs baseline: 5.4638x; 1.0283x over previous
#include <cuda_runtime.h>
#include <cuda_fp16.h>
#include <cstdint>
#include <mma.h>

using namespace nvcuda;

#define ATTN_SCALE 0.044194173824159216f  // 1/sqrt(512)
#define TH_LD 520
#define SS_LD 100

// ---------------- static device scratch ----------------
__device__ __align__(16) __half g_xhi  [768 * 512],   g_xlo  [768 * 512];
__device__ __align__(16) __half g_siwhi[1536 * 512],  g_siwlo[1536 * 512];
__device__ __align__(16) __half g_sowhi[512 * 512],   g_sowlo[512 * 512];
__device__ __align__(16) __half g_cWkhi[512 * 512],   g_cWklo[512 * 512];
__device__ __align__(16) __half g_cWvhi[512 * 512],   g_cWvlo[512 * 512];
__device__ __align__(16) __half g_cWqThi[512 * 512],  g_cWqTlo[512 * 512];
__device__ __align__(16) __half g_cowhi[512 * 512],   g_cowlo[512 * 512];
__device__ __align__(16) float  g_qkv  [768 * 1536];
__device__ __align__(16) __half g_aohi [768 * 512],   g_aolo [768 * 512];
__device__ __align__(16) float  g_xs   [768 * 512];
__device__ __align__(16) __half g_xshi [768 * 512],   g_xslo [768 * 512];
__device__ __align__(16) __half g_W2hi [512 * 512],   g_W2lo [512 * 512];
__device__ __align__(16) float  g_bqk  [512];
__device__ __align__(16) __half g_qkh  [768 * 512];
__device__ __align__(16) __half g_Wovh [512 * 512];
__device__ __align__(16) float  g_bov  [512];
__device__ __align__(16) __half g_rch  [(size_t)64 * 1000 * 512];
__device__ __align__(16) __half g_txth [(size_t)64 * 1000 * 512];
__device__ __align__(16) float  g_part [8 * 64 * 512];
__device__ __align__(16) float  g_h    [64 * 512];

// ---------------- helpers ----------------
__device__ __forceinline__ void cpasync16(uint32_t dst, const void* src) {
    asm volatile("cp.async.cg.shared.global [%0], [%1], 16;"
                 :: "r"(dst), "l"(__cvta_generic_to_global(src)));
}
__device__ __forceinline__ uint32_t smem_u32(const void* p) {
    uint32_t a;
    asm("{ .reg .u64 t; cvta.to.shared.u64 t, %1; cvt.u32.u64 %0, t; }" : "=r"(a) : "l"(p));
    return a;
}
#define CP_COMMIT() asm volatile("cp.async.commit_group;" ::: "memory")
#define CP_WAIT0()  asm volatile("cp.async.wait_group 0;" ::: "memory")

__device__ __forceinline__ void split_f(float x, __half& h, __half& l) {
    h = __float2half(x);
    l = __float2half(x - __half2float(h));
}

// =======================================================================
// fp32 -> (hi, lo) fp16 split convert
// =======================================================================
__global__ void f2h_split(const float* __restrict__ in,
                          __half* __restrict__ hi, __half* __restrict__ lo, size_t n)
{
    size_t i = ((size_t)blockIdx.x * blockDim.x + threadIdx.x) * 4;
    if (i >= n) return;
    float4 v = *(const float4*)(in + i);
    __half h0, l0, h1, l1, h2, l2, h3, l3;
    split_f(v.x, h0, l0); split_f(v.y, h1, l1);
    split_f(v.z, h2, l2); split_f(v.w, h3, l3);
    __half2* oh = (__half2*)(hi + i);
    __half2* ol = (__half2*)(lo + i);
    oh[0] = __halves2half2(h0, h1); oh[1] = __halves2half2(h2, h3);
    ol[0] = __halves2half2(l0, l1); ol[1] = __halves2half2(l2, l3);
}

// 512x512 transpose + split: out[m,k] = in[k,m]
__global__ void f2h_t_split(const float* __restrict__ in,
                            __half* __restrict__ hi, __half* __restrict__ lo)
{
    __shared__ float t[32][33];
    const int tx = threadIdx.x & 31, ty = threadIdx.x >> 5;
    const int bx = blockIdx.x * 32, by = blockIdx.y * 32;
    #pragma unroll
    for (int j = 0; j < 4; j++)
        t[ty + j * 8][tx] = in[(size_t)(by + ty + j * 8) * 512 + bx + tx];
    __syncthreads();
    #pragma unroll
    for (int j = 0; j < 4; j++) {
        float v = t[tx][ty + j * 8];
        __half h, l; split_f(v, h, l);
        size_t o = (size_t)(bx + ty + j * 8) * 512 + by + tx;
        hi[o] = h; lo[o] = l;
    }
}

// =======================================================================
// Split-fp16 GEMM: C = scale*(Ahi+Alo)(Bhi+Blo) + bias, f32 accumulate.
// Tile 64x64, k-chunk 64, 256 threads. bt=1: B [N,K]; bt=0: B [K,N].
// Outputs: optional f32 Cf, fp16 Chi, fp16 residual Clo.
// =======================================================================
__global__ void hgemm3(const __half* __restrict__ Ahi, const __half* __restrict__ Alo,
                       const __half* __restrict__ Bhi, const __half* __restrict__ Blo, int bt,
                       const float* __restrict__ bias, float scale,
                       float* __restrict__ Cf, __half* __restrict__ Chi, __half* __restrict__ Clo,
                       int N, int K)
{
    __shared__ __half Ash[64 * 72], Asl[64 * 72];
    __shared__ __half Bsh[64 * 72], Bsl[64 * 72];
    __shared__ float  Cs[64 * 68];
    const int tid = threadIdx.x, warp = tid >> 5;
    const int m0 = blockIdx.y * 64, n0 = blockIdx.x * 64;
    const int wr = warp >> 1, wc = warp & 1;

    wmma::fragment<wmma::accumulator, 16, 16, 16, float> acc[2];
    wmma::fill_fragment(acc[0], 0.f);
    wmma::fill_fragment(acc[1], 0.f);

    uint4 rah[2], ral[2], rbh[2], rbl[2];
    #pragma unroll
    for (int i = 0; i < 2; i++) {
        int f = tid + i * 256, r = f >> 3, v = f & 7;
        rah[i] = ((const uint4*)(Ahi + (size_t)(m0 + r) * K))[v];
        ral[i] = ((const uint4*)(Alo + (size_t)(m0 + r) * K))[v];
        if (bt) {
            rbh[i] = ((const uint4*)(Bhi + (size_t)(n0 + r) * K))[v];
            rbl[i] = ((const uint4*)(Blo + (size_t)(n0 + r) * K))[v];
        } else {
            rbh[i] = ((const uint4*)(Bhi + (size_t)r * N + n0))[v];
            rbl[i] = ((const uint4*)(Blo + (size_t)r * N + n0))[v];
        }
    }
    const int nk = K >> 6;
    for (int kc = 0; kc < nk; kc++) {
        #pragma unroll
        for (int i = 0; i < 2; i++) {
            int f = tid + i * 256, r = f >> 3, v = f & 7;
            *((uint4*)(Ash + r * 72) + v) = rah[i];
            *((uint4*)(Asl + r * 72) + v) = ral[i];
            *((uint4*)(Bsh + r * 72) + v) = rbh[i];
            *((uint4*)(Bsl + r * 72) + v) = rbl[i];
        }
        __syncthreads();
        if (kc + 1 < nk) {
            int kk = (kc + 1) << 6;
            #pragma unroll
            for (int i = 0; i < 2; i++) {
                int f = tid + i * 256, r = f >> 3, v = f & 7;
                rah[i] = ((const uint4*)(Ahi + (size_t)(m0 + r) * K + kk))[v];
                ral[i] = ((const uint4*)(Alo + (size_t)(m0 + r) * K + kk))[v];
                if (bt) {
                    rbh[i] = ((const uint4*)(Bhi + (size_t)(n0 + r) * K + kk))[v];
                    rbl[i] = ((const uint4*)(Blo + (size_t)(n0 + r) * K + kk))[v];
                } else {
                    rbh[i] = ((const uint4*)(Bhi + (size_t)(kk + r) * N + n0))[v];
                    rbl[i] = ((const uint4*)(Blo + (size_t)(kk + r) * N + n0))[v];
                }
            }
        }
        #pragma unroll
        for (int ks = 0; ks < 4; ks++) {
            wmma::fragment<wmma::matrix_a, 16, 16, 16, __half, wmma::row_major> afh, afl;
            wmma::load_matrix_sync(afh, Ash + (wr * 16) * 72 + ks * 16, 72);
            wmma::load_matrix_sync(afl, Asl + (wr * 16) * 72 + ks * 16, 72);
            #pragma unroll
            for (int j = 0; j < 2; j++) {
                if (bt) {
                    wmma::fragment<wmma::matrix_b, 16, 16, 16, __half, wmma::col_major> bfh, bfl;
                    wmma::load_matrix_sync(bfh, Bsh + ((wc * 2 + j) * 16) * 72 + ks * 16, 72);
                    wmma::load_matrix_sync(bfl, Bsl + ((wc * 2 + j) * 16) * 72 + ks * 16, 72);
                    wmma::mma_sync(acc[j], afh, bfh, acc[j]);
                    wmma::mma_sync(acc[j], afh, bfl, acc[j]);
                    wmma::mma_sync(acc[j], afl, bfh, acc[j]);
                } else {
                    wmma::fragment<wmma::matrix_b, 16, 16, 16, __half, wmma::row_major> bfh, bfl;
                    wmma::load_matrix_sync(bfh, Bsh + (ks * 16) * 72 + (wc * 2 + j) * 16, 72);
                    wmma::load_matrix_sync(bfl, Bsl + (ks * 16) * 72 + (wc * 2 + j) * 16, 72);
                    wmma::mma_sync(acc[j], afh, bfh, acc[j]);
                    wmma::mma_sync(acc[j], afh, bfl, acc[j]);
                    wmma::mma_sync(acc[j], afl, bfh, acc[j]);
                }
            }
        }
        __syncthreads();
    }
    wmma::store_matrix_sync(Cs + (wr * 16) * 68 + wc * 32,      acc[0], 68, wmma::mem_row_major);
    wmma::store_matrix_sync(Cs + (wr * 16) * 68 + wc * 32 + 16, acc[1], 68, wmma::mem_row_major);
    __syncthreads();
    for (int i = tid; i < 4096; i += 256) {
        int r = i >> 6, n = i & 63;
        float v = Cs[r * 68 + n] * scale + (bias ? bias[n0 + n] : 0.f);
        size_t m = m0 + r;
        if (Cf)  Cf[m * N + n0 + n] = v;
        if (Chi) {
            __half h = __float2half(v);
            Chi[m * N + n0 + n] = h;
            if (Clo) Clo[m * N + n0 + n] = __float2half(v - __half2float(h));
        }
    }
}

// =======================================================================
// self-attention over the 12-layer axis; reads g_qkv f32, writes ao hi/lo
// =======================================================================
__global__ void self_attn_kernel()
{
    extern __shared__ float sh[];
    float* q = sh;
    float* k = q + 12 * 512;
    float* v = k + 12 * 512;
    float* S = v + 12 * 512;
    const int b = blockIdx.x, tid = threadIdx.x;
    for (int i = tid; i < 12 * 512; i += 128) {
        int l = i >> 9, d = i & 511;
        const float* row = g_qkv + (size_t)(l * 64 + b) * 1536;
        q[i] = row[d]; k[i] = row[512 + d]; v[i] = row[1024 + d];
    }
    __syncthreads();
    for (int i = tid; i < 144; i += 128) {
        int l = i / 12, m = i - l * 12;
        const float* qp = q + l * 512;
        const float* kp = k + m * 512;
        float s = 0.f;
        for (int e = 0; e < 512; e++) s += qp[e] * kp[e];
        S[i] = s * ATTN_SCALE;
    }
    __syncthreads();
    if (tid < 12) {
        float mx = -1e30f;
        for (int m = 0; m < 12; m++) mx = fmaxf(mx, S[tid * 12 + m]);
        float e[12], sum = 0.f;
        for (int m = 0; m < 12; m++) { e[m] = expf(S[tid * 12 + m] - mx); sum += e[m]; }
        float inv = 1.f / sum;
        for (int m = 0; m < 12; m++) S[tid * 12 + m] = e[m] * inv;
    }
    __syncthreads();
    for (int i = tid; i < 12 * 512; i += 128) {
        int l = i >> 9, d = i & 511;
        float o = 0.f;
        #pragma unroll
        for (int m = 0; m < 12; m++) o += S[l * 12 + m] * v[m * 512 + d];
        __half h, lo; split_f(o, h, lo);
        size_t idx = (size_t)(b * 12 + l) * 512 + d;
        g_aohi[idx] = h; g_aolo[idx] = lo;
    }
}

// bqk: f32, grid 16 x 256
__global__ void bqk_kernel(const float* __restrict__ ciw, const float* __restrict__ cib)
{
    __shared__ float red[8][33];
    const int dd = threadIdx.x & 31, eg = threadIdx.x >> 5;
    const int d = blockIdx.x * 32 + dd;
    const float* cWk = ciw + 512 * 512;
    float s = 0.f;
    const int e0 = eg * 64;
    #pragma unroll 8
    for (int e = e0; e < e0 + 64; e++) s += cib[e] * cWk[(size_t)e * 512 + d];
    red[eg][dd] = s;
    __syncthreads();
    if (eg == 0) {
        float t = 0.f;
        #pragma unroll
        for (int i = 0; i < 8; i++) t += red[i][dd];
        g_bqk[d] = t * ATTN_SCALE;
    }
}

// bov: warp per output
__global__ void bov_kernel(const float* __restrict__ cow,
                           const float* __restrict__ cib,
                           const float* __restrict__ cob)
{
    int warp = threadIdx.x >> 5, lane = threadIdx.x & 31;
    int i = blockIdx.x * 8 + warp;
    const float* cbv = cib + 1024;
    float s = 0.f;
    for (int e = lane; e < 512; e += 32) s += cow[i * 512 + e] * cbv[e];
    #pragma unroll
    for (int o = 16; o > 0; o >>= 1) s += __shfl_xor_sync(0xffffffff, s, o);
    if (lane == 0) g_bov[i] = s + cob[i];
}

// =======================================================================
// Fused cross-attention (unchanged from R6's 706us version)
// =======================================================================
#define AQ0 99840
#define AQB 27648
#define WSM 176640

__global__ void attn_cls_kernel(const float* __restrict__ textf)
{
    extern __shared__ char smc[];
    __half* th  = (__half*)smc;
    float*  Ss  = (float*)(smc + AQ0);
    __half* wsm = (__half*)(smc + WSM);
    const uint32_t aqs = smem_u32(smc) + AQ0;
    const int tid  = threadIdx.x;
    const int warp = tid >> 5;
    const int c    = blockIdx.x;
    const int wr = warp >> 1, wc = warp & 1;

    {
        const float4* src = (const float4*)(textf + (size_t)c * (96 * 512));
        for (int i = tid; i < 96 * 128; i += 256) {
            int row = i >> 7, v = i & 127;
            float4 f = src[row * 128 + v];
            __half2* dst = (__half2*)(th + row * TH_LD + v * 4);
            dst[0] = __floats2half2_rn(f.x, f.y);
            dst[1] = __floats2half2_rn(f.z, f.w);
        }
    }
    __syncthreads();

    for (int mch = 0; mch < 4; mch++) {
        const int b0 = mch * 16;
        const __half* qbase = g_qkh + (size_t)(b0 * 12) * 512;

        #pragma unroll
        for (int i = 0; i < 6; i++) {
            int f = tid + i * 256, r = f >> 3, v = f & 7;
            cpasync16(aqs + r * 144 + v * 16, qbase + (size_t)r * 512 + v * 8);
        }
        CP_COMMIT();

        wmma::fragment<wmma::accumulator, 16, 16, 16, float> acc[3][3];
        #pragma unroll
        for (int i = 0; i < 3; i++)
            #pragma unroll
            for (int j = 0; j < 3; j++) wmma::fill_fragment(acc[i][j], 0.f);

        for (int kc = 0; kc < 8; kc++) {
            CP_WAIT0();
            __syncthreads();
            if (kc < 7) {
                uint32_t nbuf = aqs + ((kc + 1) & 1) * AQB;
                #pragma unroll
                for (int i = 0; i < 6; i++) {
                    int f = tid + i * 256, r = f >> 3, v = f & 7;
                    cpasync16(nbuf + r * 144 + v * 16,
                              qbase + (size_t)r * 512 + (kc + 1) * 64 + v * 8);
                }
                CP_COMMIT();
            }
            const __half* aq = (const __half*)(smc + AQ0 + (kc & 1) * AQB);
            #pragma unroll
            for (int ks = 0; ks < 4; ks++) {
                wmma::fragment<wmma::matrix_a, 16, 16, 16, __half, wmma::row_major> af[3];
                #pragma unroll
                for (int i = 0; i < 3; i++)
                    wmma::load_matrix_sync(af[i], aq + ((wr * 3 + i) * 16) * 72 + ks * 16, 72);
                #pragma unroll
                for (int j = 0; j < 3; j++) {
                    wmma::fragment<wmma::matrix_b, 16, 16, 16, __half, wmma::col_major> bf;
                    wmma::load_matrix_sync(bf, th + ((wc * 3 + j) * 16) * TH_LD + kc * 64 + ks * 16, TH_LD);
                    #pragma unroll
                    for (int i = 0; i < 3; i++) wmma::mma_sync(acc[i][j], af[i], bf, acc[i][j]);
                }
            }
        }
        __syncthreads();
        #pragma unroll
        for (int i = 0; i < 3; i++)
            #pragma unroll
            for (int j = 0; j < 3; j++)
                wmma::store_matrix_sync(Ss + ((wr * 3 + i) * 16) * SS_LD + (wc * 3 + j) * 16,
                                        acc[i][j], SS_LD, wmma::mem_row_major);
        __syncthreads();

        if (tid < 128) {
            int bl = tid >> 3, t = tid & 7;
            float wacc[12];
            #pragma unroll
            for (int m = 0; m < 12; m++) wacc[m] = 0.f;
            for (int l = 0; l < 12; l++) {
                int base = (bl * 12 + l) * SS_LD + t;
                float vals[12], mx = -1e30f;
                #pragma unroll
                for (int m = 0; m < 12; m++) { vals[m] = Ss[base + m * 8]; mx = fmaxf(mx, vals[m]); }
                float sum = 0.f;
                #pragma unroll
                for (int m = 0; m < 12; m++) { vals[m] = __expf(vals[m] - mx); sum += vals[m]; }
                float inv = 1.f / sum;
                #pragma unroll
                for (int m = 0; m < 12; m++) wacc[m] += vals[m] * inv;
            }
            #pragma unroll
            for (int m = 0; m < 12; m++)
                wsm[bl * 96 + m * 8 + t] = __float2half(wacc[m] * (1.f / 96.f));
        }
        __syncthreads();

        {
            wmma::fragment<wmma::accumulator, 16, 16, 16, float> rca[4];
            #pragma unroll
            for (int j = 0; j < 4; j++) wmma::fill_fragment(rca[j], 0.f);
            #pragma unroll
            for (int kt = 0; kt < 6; kt++) {
                wmma::fragment<wmma::matrix_a, 16, 16, 16, __half, wmma::row_major> af;
                wmma::load_matrix_sync(af, wsm + kt * 16, 96);
                #pragma unroll
                for (int j = 0; j < 4; j++) {
                    wmma::fragment<wmma::matrix_b, 16, 16, 16, __half, wmma::row_major> bf;
                    wmma::load_matrix_sync(bf, th + (kt * 16) * TH_LD + (warp * 4 + j) * 16, TH_LD);
                    wmma::mma_sync(rca[j], af, bf, rca[j]);
                }
            }
            #pragma unroll
            for (int j = 0; j < 4; j++)
                wmma::store_matrix_sync(Ss + (warp * 4 + j) * 16, rca[j], TH_LD, wmma::mem_row_major);
        }
        __syncthreads();

        for (int i = tid; i < 16 * 512; i += 256) {
            int bl = i >> 9, d = i & 511;
            g_rch[((size_t)(b0 + bl) * 1000 + c) * 512 + d] = __float2half(Ss[bl * TH_LD + d]);
        }
        __syncthreads();
    }
}

// =======================================================================
// txt = rc @ Wov^T + bov -> fp16 g_txth. grid (4,500).
// =======================================================================
__global__ void txt_gemm_kernel()
{
    __shared__ __half As[128 * 72];
    __shared__ __half Bs[128 * 72];
    __shared__ float  stg[8][16 * 20];
    const int tid = threadIdx.x, warp = tid >> 5, lane = tid & 31;
    const size_t m0 = (size_t)blockIdx.y * 128;
    const int n0 = blockIdx.x * 128;
    const int wr = warp >> 1, wc = warp & 1;
    uint4 ra[4], rb[4];
    wmma::fragment<wmma::accumulator, 16, 16, 16, float> acc[2][4];
    #pragma unroll
    for (int i = 0; i < 2; i++)
        #pragma unroll
        for (int j = 0; j < 4; j++) wmma::fill_fragment(acc[i][j], 0.f);

    #pragma unroll
    for (int i = 0; i < 4; i++) {
        int f = tid + i * 256, r = f >> 3, v = f & 7;
        ra[i] = ((const uint4*)(g_rch + (m0 + r) * 512))[v];
        rb[i] = ((const uint4*)(g_Wovh + (size_t)(n0 + r) * 512))[v];
    }
    for (int kc = 0; kc < 8; kc++) {
        #pragma unroll
        for (int i = 0; i < 4; i++) {
            int f = tid + i * 256, r = f >> 3, v = f & 7;
            *((uint4*)(As + r * 72) + v) = ra[i];
            *((uint4*)(Bs + r * 72) + v) = rb[i];
        }
        __syncthreads();
        if (kc < 7) {
            int kk = (kc + 1) * 64;
            #pragma unroll
            for (int i = 0; i < 4; i++) {
                int f = tid + i * 256, r = f >> 3, v = f & 7;
                ra[i] = ((const uint4*)(g_rch + (m0 + r) * 512 + kk))[v];
                rb[i] = ((const uint4*)(g_Wovh + (size_t)(n0 + r) * 512 + kk))[v];
            }
        }
        #pragma unroll
        for (int ks = 0; ks < 4; ks++) {
            wmma::fragment<wmma::matrix_a, 16, 16, 16, __half, wmma::row_major> af[2];
            #pragma unroll
            for (int i = 0; i < 2; i++)
                wmma::load_matrix_sync(af[i], As + ((wr * 2 + i) * 16) * 72 + ks * 16, 72);
            #pragma unroll
            for (int j = 0; j < 4; j++) {
                wmma::fragment<wmma::matrix_b, 16, 16, 16, __half, wmma::col_major> bf;
                wmma::load_matrix_sync(bf, Bs + ((wc * 4 + j) * 16) * 72 + ks * 16, 72);
                #pragma unroll
                for (int i = 0; i < 2; i++) wmma::mma_sync(acc[i][j], af[i], bf, acc[i][j]);
            }
        }
        __syncthreads();
    }
    // epilogue: +bov, fp16 store
    #pragma unroll
    for (int i = 0; i < 2; i++)
        #pragma unroll
        for (int j = 0; j < 4; j++) {
            wmma::store_matrix_sync(stg[warp], acc[i][j], 20, wmma::mem_row_major);
            __syncwarp();
            #pragma unroll
            for (int e = 0; e < 8; e++) {
                int f = lane + e * 32, r = f >> 4, cc = f & 15;
                int n = n0 + (wc * 4 + j) * 16 + cc;
                float v = stg[warp][r * 20 + cc] + g_bov[n];
                g_txth[(m0 + (wr * 2 + i) * 16 + r) * 512 + n] = __float2half(v);
            }
            __syncwarp();
        }
}

// partial column-norms over 125-class chunks (half2 reads)
__global__ void colnorm_partial()
{
    const int b = blockIdx.y, chunk = blockIdx.x, d2 = threadIdx.x;  // 256 thr
    const int cs = chunk * 125;
    const __half2* base = (const __half2*)g_txth + ((size_t)b * 1000 + cs) * 256 + d2;
    float ax = 0.f, ay = 0.f;
    for (int c = 0; c < 125; c++) {
        float2 f = __half22float2(base[(size_t)c * 256]);
        ax += f.x * f.x; ay += f.y * f.y;
    }
    float2* o = (float2*)(g_part + (size_t)(chunk * 64 + b) * 512) + d2;
    *o = make_float2(ax, ay);
}

__global__ void make_h_kernel()
{
    __shared__ float red[512];
    const int b = blockIdx.x, d = threadIdx.x;
    float nrm2 = 0.f;
    #pragma unroll
    for (int p = 0; p < 8; p++) nrm2 += g_part[(size_t)(p * 64 + b) * 512 + d];
    float iv = g_xs[(size_t)(b * 12 + 11) * 512 + d];
    red[d] = iv * iv;
    __syncthreads();
    for (int s = 256; s > 0; s >>= 1) {
        if (d < s) red[d] += red[d + s];
        __syncthreads();
    }
    g_h[b * 512 + d] = iv * rsqrtf(red[0]) * rsqrtf(nrm2);
}

__global__ void logits_kernel(const float* __restrict__ ls, float* __restrict__ out)
{
    __shared__ float hs[512];
    const int b = blockIdx.y;
    const int tid = threadIdx.x, warp = tid >> 5, lane = tid & 31;
    const int c = blockIdx.x * 8 + warp;
    for (int i = tid; i < 512; i += 256) hs[i] = g_h[b * 512 + i];
    __syncthreads();
    const __half2* row = (const __half2*)g_txth + ((size_t)b * 1000 + c) * 256;
    float acc = 0.f;
    for (int kk = lane; kk < 256; kk += 32) {
        float2 f = __half22float2(row[kk]);
        acc += hs[kk * 2] * f.x + hs[kk * 2 + 1] * f.y;
    }
    #pragma unroll
    for (int off = 16; off > 0; off >>= 1) acc += __shfl_xor_sync(0xffffffff, acc, off);
    if (lane == 0) out[(size_t)b * 1000 + c] = expf(ls[0]) * acc;
}

// =======================================================================
extern "C" void kernel_launch(void* const* d_in, const int* in_sizes, int n_in,
                              void* d_out, int out_size)
{
    const float* x   = (const float*)d_in[0];
    const float* txt = (const float*)d_in[1];
    const float* siw = (const float*)d_in[2];
    const float* sib = (const float*)d_in[3];
    const float* sow = (const float*)d_in[4];
    const float* sob = (const float*)d_in[5];
    const float* ciw = (const float*)d_in[6];
    const float* cib = (const float*)d_in[7];
    const float* cow = (const float*)d_in[8];
    const float* cob = (const float*)d_in[9];
    const float* ls  = (const float*)d_in[10];
    float* out = (float*)d_out;

    __half *p_xhi, *p_xlo, *p_siwhi, *p_siwlo, *p_sowhi, *p_sowlo;
    __half *p_cWkhi, *p_cWklo, *p_cWvhi, *p_cWvlo, *p_cWqThi, *p_cWqTlo;
    __half *p_cowhi, *p_cowlo, *p_aohi, *p_aolo, *p_xshi, *p_xslo;
    __half *p_W2hi, *p_W2lo, *p_qkh, *p_Wovh;
    float  *p_qkv, *p_xs, *p_bqk;
    cudaGetSymbolAddress((void**)&p_xhi,    g_xhi);
    cudaGetSymbolAddress((void**)&p_xlo,    g_xlo);
    cudaGetSymbolAddress((void**)&p_siwhi,  g_siwhi);
    cudaGetSymbolAddress((void**)&p_siwlo,  g_siwlo);
    cudaGetSymbolAddress((void**)&p_sowhi,  g_sowhi);
    cudaGetSymbolAddress((void**)&p_sowlo,  g_sowlo);
    cudaGetSymbolAddress((void**)&p_cWkhi,  g_cWkhi);
    cudaGetSymbolAddress((void**)&p_cWklo,  g_cWklo);
    cudaGetSymbolAddress((void**)&p_cWvhi,  g_cWvhi);
    cudaGetSymbolAddress((void**)&p_cWvlo,  g_cWvlo);
    cudaGetSymbolAddress((void**)&p_cWqThi, g_cWqThi);
    cudaGetSymbolAddress((void**)&p_cWqTlo, g_cWqTlo);
    cudaGetSymbolAddress((void**)&p_cowhi,  g_cowhi);
    cudaGetSymbolAddress((void**)&p_cowlo,  g_cowlo);
    cudaGetSymbolAddress((void**)&p_aohi,   g_aohi);
    cudaGetSymbolAddress((void**)&p_aolo,   g_aolo);
    cudaGetSymbolAddress((void**)&p_xshi,   g_xshi);
    cudaGetSymbolAddress((void**)&p_xslo,   g_xslo);
    cudaGetSymbolAddress((void**)&p_W2hi,   g_W2hi);
    cudaGetSymbolAddress((void**)&p_W2lo,   g_W2lo);
    cudaGetSymbolAddress((void**)&p_qkh,    g_qkh);
    cudaGetSymbolAddress((void**)&p_Wovh,   g_Wovh);
    cudaGetSymbolAddress((void**)&p_qkv,    g_qkv);
    cudaGetSymbolAddress((void**)&p_xs,     g_xs);
    cudaGetSymbolAddress((void**)&p_bqk,    g_bqk);

    cudaFuncSetAttribute(self_attn_kernel, cudaFuncAttributeMaxDynamicSharedMemorySize, 74304);
    cudaFuncSetAttribute(attn_cls_kernel,  cudaFuncAttributeMaxDynamicSharedMemorySize, 188928);

    // ---- split conversions ----
    f2h_split<<<384, 256>>>(x,   p_xhi,   p_xlo,   (size_t)768 * 512);
    f2h_split<<<768, 256>>>(siw, p_siwhi, p_siwlo, (size_t)1536 * 512);
    f2h_split<<<256, 256>>>(sow, p_sowhi, p_sowlo, (size_t)512 * 512);
    f2h_split<<<256, 256>>>(ciw + 512 * 512,  p_cWkhi, p_cWklo, (size_t)512 * 512);
    f2h_split<<<256, 256>>>(ciw + 1024 * 512, p_cWvhi, p_cWvlo, (size_t)512 * 512);
    f2h_split<<<256, 256>>>(cow, p_cowhi, p_cowlo, (size_t)512 * 512);
    f2h_t_split<<<dim3(16, 16), 256>>>(ciw, p_cWqThi, p_cWqTlo);

    // ---- prologue GEMMs (split-fp16, fp32-quality) ----
    hgemm3<<<dim3(24, 12), 256>>>(p_xhi, p_xlo, p_siwhi, p_siwlo, 1, sib, 1.f,
                                  p_qkv, nullptr, nullptr, 1536, 512);
    hgemm3<<<dim3(8, 8), 256>>>(p_cWqThi, p_cWqTlo, p_cWkhi, p_cWklo, 0, nullptr, ATTN_SCALE,
                                nullptr, p_W2hi, p_W2lo, 512, 512);
    hgemm3<<<dim3(8, 8), 256>>>(p_cowhi, p_cowlo, p_cWvhi, p_cWvlo, 0, nullptr, 1.f,
                                nullptr, p_Wovh, nullptr, 512, 512);
    bqk_kernel<<<16, 256>>>(ciw, cib);
    bov_kernel<<<64, 256>>>(cow, cib, cob);

    self_attn_kernel<<<64, 128, 74304>>>();
    // xs = ao @ sow^T + sob  (f32 + split halves)
    hgemm3<<<dim3(8, 12), 256>>>(p_aohi, p_aolo, p_sowhi, p_sowlo, 1, sob, 1.f,
                                 p_xs, p_xshi, p_xslo, 512, 512);
    // qk = xs @ W2 + bqk (pre-scaled) -> single fp16
    hgemm3<<<dim3(8, 12), 256>>>(p_xshi, p_xslo, p_W2hi, p_W2lo, 0, p_bqk, 1.f,
                                 nullptr, p_qkh, nullptr, 512, 512);

    // fused cross-attention
    attn_cls_kernel<<<1000, 256, 188928>>>(txt);

    // projection (+bov, fp16) + norms + logits
    txt_gemm_kernel<<<dim3(4, 500), 256>>>();
    colnorm_partial<<<dim3(8, 64), 256>>>();
    make_h_kernel<<<64, 512>>>();
    logits_kernel<<<dim3(125, 64), 256>>>(ls, out);
}